// round 5
// baseline (speedup 1.0000x reference)
#include <cuda_runtime.h>
#include <math.h>
#include <stdint.h>

#define Bb 8
#define Nn 4096
#define Cc 512
#define Hh 8
#define DHd 64
#define Tt (Bb*Nn)   // 32768 tokens

// Scratch (allocation-free rule: device globals)
__device__ float g_xn[Tt*Cc];                 // LayerNorm output [T,C], tf32-rounded
__device__ float g_qkv[3*Bb*Hh*DHd*Nn];       // [i][b][h][d][n] fp32 (UNnormalized q,k)
__device__ float g_y[Tt*Cc];                  // gelu(attn@v) [T,C], tf32-rounded
__device__ float g_Sp[64*8*64*64];            // partial raw S per (bh, split)
__device__ float g_ss[2*64*8*64];             // partial sum-of-squares [iq][bh][split][row]
__device__ float g_attn[64*64*64];            // softmaxed attn [bh][d][e]
__device__ float g_wq[1536*512];              // tf32-rounded qkv_w
__device__ float g_wp[512*512];               // tf32-rounded proj_w

__device__ __forceinline__ uint32_t smem_u32(const void* p) {
    uint32_t a;
    asm("{ .reg .u64 t; cvta.to.shared.u64 t, %1; cvt.u32.u64 %0, t; }"
        : "=r"(a) : "l"(p));
    return a;
}
__device__ __forceinline__ float tf32r(float f) {
    uint32_t u;
    asm("cvt.rna.tf32.f32 %0, %1;" : "=r"(u) : "f"(f));
    return __uint_as_float(u);
}
__device__ __forceinline__ void cp16(uint32_t daddr, const float* src) {
    asm volatile("{ .reg .u64 p; cvta.to.global.u64 p, %1;"
                 "  cp.async.cg.shared.global [%0], [p], 16; }"
                 :: "r"(daddr), "l"(src) : "memory");
}

// ===========================================================================
// K0: round weights to tf32 representable values (rna)
// ===========================================================================
__global__ void round_w_kernel(const float* __restrict__ qkv_w,
                               const float* __restrict__ proj_w) {
    const int n1 = 1536*512/4, n2 = 512*512/4;
    for (int i = blockIdx.x*blockDim.x + threadIdx.x; i < n1 + n2;
         i += gridDim.x*blockDim.x) {
        const float4 v = (i < n1) ? ((const float4*)qkv_w)[i]
                                  : ((const float4*)proj_w)[i - n1];
        float4 o;
        o.x = tf32r(v.x); o.y = tf32r(v.y); o.z = tf32r(v.z); o.w = tf32r(v.w);
        if (i < n1) ((float4*)g_wq)[i] = o;
        else        ((float4*)g_wp)[i - n1] = o;
    }
}

// ===========================================================================
// K1: LayerNorm (outputs tf32-rounded)
// ===========================================================================
__global__ void ln_kernel(const float* __restrict__ x,
                          const float* __restrict__ gam,
                          const float* __restrict__ bet) {
    const int t = blockIdx.x;
    const int tid = threadIdx.x;           // 128
    const float4 xv = *(const float4*)(x + (size_t)t*Cc + tid*4);
    float s  = xv.x + xv.y + xv.z + xv.w;
    float ss = xv.x*xv.x + xv.y*xv.y + xv.z*xv.z + xv.w*xv.w;
    #pragma unroll
    for (int o = 16; o > 0; o >>= 1) {
        s  += __shfl_xor_sync(0xffffffffu, s,  o);
        ss += __shfl_xor_sync(0xffffffffu, ss, o);
    }
    __shared__ float shs[4], shss[4];
    const int w = tid >> 5, l = tid & 31;
    if (l == 0) { shs[w] = s; shss[w] = ss; }
    __syncthreads();
    const float tot  = shs[0]  + shs[1]  + shs[2]  + shs[3];
    const float tots = shss[0] + shss[1] + shss[2] + shss[3];
    const float mean = tot * (1.0f/512.0f);
    const float var  = tots * (1.0f/512.0f) - mean*mean;
    const float inv  = rsqrtf(var + 1e-5f);
    const float4 gv = *(const float4*)(gam + tid*4);
    const float4 bv = *(const float4*)(bet + tid*4);
    float4 o;
    o.x = tf32r((xv.x - mean)*inv*gv.x + bv.x);
    o.y = tf32r((xv.y - mean)*inv*gv.y + bv.y);
    o.z = tf32r((xv.z - mean)*inv*gv.z + bv.z);
    o.w = tf32r((xv.w - mean)*inv*gv.w + bv.w);
    *(float4*)(g_xn + (size_t)t*Cc + tid*4) = o;
}

// ===========================================================================
// tf32 mma.sync GEMM: C[t,o] = sum_c A[t,c]*W[o,c].
// Block 128(m) x 256(n), 256 thr (8 warps, 2x4), warp tile 64x64.
// Smem [m][k] ld=36 words, cp.async 3-stage pipeline, ldmatrix frag loads.
// EPI=0: A=g_xn, W=g_wq -> scatter g_qkv.  EPI=1: A=g_y, W=g_wp -> out+bias.
// ===========================================================================
#define LDK 36
#define A_BYTES (128*LDK*4)      // 18432
#define W_BYTES (256*LDK*4)      // 36864
#define BUF_BYTES (A_BYTES + W_BYTES)  // 55296
#define GEMM_SMEM (3*BUF_BYTES)        // 165888

template<int EPI>
__global__ void __launch_bounds__(256, 1) mmagemm(const float* __restrict__ bias,
                                                  float* __restrict__ out) {
    extern __shared__ float smem[];
    const uint32_t sb = smem_u32(smem);
    const float* __restrict__ A = (EPI == 0) ? g_xn : g_y;
    const float* __restrict__ W = (EPI == 0) ? g_wq : g_wp;
    const int tid = threadIdx.x;
    const int wid = tid >> 5, lane = tid & 31;
    const int t0 = blockIdx.y * 128;
    const int o0 = blockIdx.x * 256;
    const int wm = wid >> 2, wn = wid & 3;
    const int g = lane >> 2, tg = lane & 3;

    // staging mapping
    int ra[4], ca[4], rw[8], cw[8];
    #pragma unroll
    for (int j = 0; j < 4; j++) { const int idx = j*256 + tid; ra[j] = idx >> 3; ca[j] = (idx & 7)*4; }
    #pragma unroll
    for (int j = 0; j < 8; j++) { const int idx = j*256 + tid; rw[j] = idx >> 3; cw[j] = (idx & 7)*4; }

    // ldmatrix lane base addresses
    const int l15 = lane & 15;
    const uint32_t baseA = sb + (uint32_t)(((wm*64 + l15)*LDK + ((lane & 16) ? 4 : 0)) * 4);
    const int l7 = lane & 7;
    const uint32_t baseB = sb + A_BYTES + (uint32_t)(((wn*64 + l7)*LDK + ((lane & 8) ? 4 : 0)) * 4);

    float acc[4][8][4];
    #pragma unroll
    for (int mt = 0; mt < 4; mt++)
        #pragma unroll
        for (int nt = 0; nt < 8; nt++)
            #pragma unroll
            for (int r = 0; r < 4; r++) acc[mt][nt][r] = 0.0f;

    // prologue: stage tiles 0,1 into buffers 0,1
    #pragma unroll
    for (int s = 0; s < 2; s++) {
        const uint32_t sA = sb + s*BUF_BYTES, sW = sA + A_BYTES;
        const int k0 = s * 32;
        #pragma unroll
        for (int j = 0; j < 4; j++)
            cp16(sA + (ra[j]*LDK + ca[j])*4, A + (size_t)(t0 + ra[j])*512 + k0 + ca[j]);
        #pragma unroll
        for (int j = 0; j < 8; j++)
            cp16(sW + (rw[j]*LDK + cw[j])*4, W + (size_t)(o0 + rw[j])*512 + k0 + cw[j]);
        asm volatile("cp.async.commit_group;" ::: "memory");
    }

    for (int c = 0; c < 16; c++) {
        if (c < 15) asm volatile("cp.async.wait_group 1;" ::: "memory");
        else        asm volatile("cp.async.wait_group 0;" ::: "memory");
        __syncthreads();
        if (c + 2 < 16) {
            const int k0 = (c + 2) * 32;
            const uint32_t sA = sb + ((c + 2) % 3)*BUF_BYTES;
            const uint32_t sW = sA + A_BYTES;
            #pragma unroll
            for (int j = 0; j < 4; j++)
                cp16(sA + (ra[j]*LDK + ca[j])*4, A + (size_t)(t0 + ra[j])*512 + k0 + ca[j]);
            #pragma unroll
            for (int j = 0; j < 8; j++)
                cp16(sW + (rw[j]*LDK + cw[j])*4, W + (size_t)(o0 + rw[j])*512 + k0 + cw[j]);
            asm volatile("cp.async.commit_group;" ::: "memory");
        }
        const uint32_t aoff = baseA + (c % 3)*BUF_BYTES;
        const uint32_t boff = baseB + (c % 3)*BUF_BYTES;
        #pragma unroll
        for (int ks = 0; ks < 4; ks++) {
            uint32_t a[4][4], b[8][2];
            #pragma unroll
            for (int mt = 0; mt < 4; mt++) {
                const uint32_t ad = aoff + (uint32_t)((mt*16*LDK + ks*8) * 4);
                asm volatile("ldmatrix.sync.aligned.m8n8.x4.shared.b16 {%0,%1,%2,%3}, [%4];"
                    : "=r"(a[mt][0]), "=r"(a[mt][1]), "=r"(a[mt][2]), "=r"(a[mt][3]) : "r"(ad));
            }
            #pragma unroll
            for (int nt = 0; nt < 8; nt++) {
                const uint32_t bd = boff + (uint32_t)((nt*8*LDK + ks*8) * 4);
                asm volatile("ldmatrix.sync.aligned.m8n8.x2.shared.b16 {%0,%1}, [%2];"
                    : "=r"(b[nt][0]), "=r"(b[nt][1]) : "r"(bd));
            }
            #pragma unroll
            for (int mt = 0; mt < 4; mt++)
                #pragma unroll
                for (int nt = 0; nt < 8; nt++) {
                    asm volatile(
                        "mma.sync.aligned.m16n8k8.row.col.f32.tf32.tf32.f32 "
                        "{%0,%1,%2,%3}, {%4,%5,%6,%7}, {%8,%9}, {%0,%1,%2,%3};"
                        : "+f"(acc[mt][nt][0]), "+f"(acc[mt][nt][1]),
                          "+f"(acc[mt][nt][2]), "+f"(acc[mt][nt][3])
                        : "r"(a[mt][0]), "r"(a[mt][1]), "r"(a[mt][2]), "r"(a[mt][3]),
                          "r"(b[nt][0]), "r"(b[nt][1]));
                }
        }
    }

    // ---- epilogue (direct global stores) ----
    const int m0g = t0 + wm*64;
    const int o0g = o0 + wn*64;
    if (EPI == 0) {
        const int i_ = o0g >> 9;
        const int h  = (o0g >> 6) & 7;
        const int b  = m0g >> 12;                 // whole block same batch
        const int rowbase = ((i_*8 + b)*8 + h) * 64;
        #pragma unroll
        for (int mt = 0; mt < 4; mt++) {
            const int t1 = m0g + mt*16 + g;
            const int n1 = t1 & 4095;
            #pragma unroll
            for (int nt = 0; nt < 8; nt++) {
                const int row = rowbase + nt*8 + tg*2;
                g_qkv[(size_t)row*4096 + n1]            = acc[mt][nt][0];
                g_qkv[(size_t)(row + 1)*4096 + n1]      = acc[mt][nt][1];
                g_qkv[(size_t)row*4096 + n1 + 8]        = acc[mt][nt][2];
                g_qkv[(size_t)(row + 1)*4096 + n1 + 8]  = acc[mt][nt][3];
            }
        }
    } else {
        #pragma unroll
        for (int mt = 0; mt < 4; mt++) {
            const int t1 = m0g + mt*16 + g;
            #pragma unroll
            for (int nt = 0; nt < 8; nt++) {
                const int o = o0g + nt*8 + tg*2;
                const float b0 = bias[o], b1 = bias[o + 1];
                float2 v0; v0.x = acc[mt][nt][0] + b0; v0.y = acc[mt][nt][1] + b1;
                float2 v1; v1.x = acc[mt][nt][2] + b0; v1.y = acc[mt][nt][3] + b1;
                *(float2*)(out + (size_t)t1*512 + o)       = v0;
                *(float2*)(out + (size_t)(t1 + 8)*512 + o) = v1;
            }
        }
    }
}

// ===========================================================================
// K4a: raw partial S = q k^T over a 512-token slice + per-row sum-of-squares
// partials for q and k. grid (64 bh, 8 splits), 256 thr.
// ===========================================================================
#define PAD 76
__global__ void __launch_bounds__(256) attn_qk_kernel() {
    __shared__ float qs[64*PAD];
    __shared__ float ks[64*PAD];
    const int bh = blockIdx.x;
    const int split = blockIdx.y;
    const float* __restrict__ q = g_qkv + (size_t)bh * 64 * 4096;
    const float* __restrict__ k = g_qkv + (size_t)(64 + bh) * 64 * 4096;
    const int tid = threadIdx.x;
    const int tx = tid & 15, ty = tid >> 4;

    float S[4][4];
    #pragma unroll
    for (int i = 0; i < 4; i++)
        #pragma unroll
        for (int j = 0; j < 4; j++) S[i][j] = 0.0f;
    float ssq[4] = {0,0,0,0}, ssk[4] = {0,0,0,0};

    const int nbeg = split * 512;
    for (int n0 = nbeg; n0 < nbeg + 512; n0 += 64) {
        #pragma unroll
        for (int j = 0; j < 4; j++) {
            const int r = j*16 + ty;
            const int c = tx*4;
            const float4 qv = *(const float4*)(q + (size_t)r*4096 + n0 + c);
            *(float4*)&qs[r*PAD + c] = qv;
            ssq[j] += qv.x*qv.x + qv.y*qv.y + qv.z*qv.z + qv.w*qv.w;
            const float4 kv = *(const float4*)(k + (size_t)r*4096 + n0 + c);
            *(float4*)&ks[r*PAD + c] = kv;
            ssk[j] += kv.x*kv.x + kv.y*kv.y + kv.z*kv.z + kv.w*kv.w;
        }
        __syncthreads();
        #pragma unroll 4
        for (int n = 0; n < 64; n += 4) {
            float4 qr[4], kr[4];
            #pragma unroll
            for (int i = 0; i < 4; i++) qr[i] = *(const float4*)&qs[(ty*4+i)*PAD + n];
            #pragma unroll
            for (int j = 0; j < 4; j++) kr[j] = *(const float4*)&ks[(tx*4+j)*PAD + n];
            #pragma unroll
            for (int i = 0; i < 4; i++)
                #pragma unroll
                for (int j = 0; j < 4; j++) {
                    S[i][j] = fmaf(qr[i].x, kr[j].x, S[i][j]);
                    S[i][j] = fmaf(qr[i].y, kr[j].y, S[i][j]);
                    S[i][j] = fmaf(qr[i].z, kr[j].z, S[i][j]);
                    S[i][j] = fmaf(qr[i].w, kr[j].w, S[i][j]);
                }
        }
        __syncthreads();
    }
    // reduce ss over the 16 lanes sharing each row group
    #pragma unroll
    for (int o = 1; o < 16; o <<= 1) {
        #pragma unroll
        for (int j = 0; j < 4; j++) {
            ssq[j] += __shfl_xor_sync(0xffffffffu, ssq[j], o);
            ssk[j] += __shfl_xor_sync(0xffffffffu, ssk[j], o);
        }
    }
    if (tx == 0) {
        #pragma unroll
        for (int j = 0; j < 4; j++) {
            const int r = j*16 + ty;
            g_ss[(size_t)bh*512 + split*64 + r]            = ssq[j];
            g_ss[(size_t)(64 + bh)*512 + split*64 + r]     = ssk[j];
        }
    }
    float* dst = g_Sp + ((size_t)(bh*8 + split)) * 4096;
    #pragma unroll
    for (int i = 0; i < 4; i++) {
        float4 v;
        v.x = S[i][0]; v.y = S[i][1]; v.z = S[i][2]; v.w = S[i][3];
        *(float4*)(dst + (ty*4+i)*64 + tx*4) = v;
    }
}

// ===========================================================================
// K4b: reduce 8 partials, apply norm scales * temperature, softmax over e.
// ===========================================================================
#define PAD2 65
__global__ void __launch_bounds__(256) softmax_kernel(const float* __restrict__ temperature) {
    __shared__ float S[64*PAD2];
    __shared__ float scq[64], sck[64];
    const int bh = blockIdx.x;
    const int tid = threadIdx.x;
    for (int idx = tid; idx < 4096; idx += 256) {
        float s = 0.0f;
        #pragma unroll
        for (int sp = 0; sp < 8; sp++)
            s += g_Sp[((size_t)(bh*8 + sp))*4096 + idx];
        S[(idx >> 6)*PAD2 + (idx & 63)] = s;
    }
    if (tid < 128) {
        const int iq = tid >> 6;          // 0=q, 1=k
        const int r = tid & 63;
        float s = 0.0f;
        #pragma unroll
        for (int sp = 0; sp < 8; sp++)
            s += g_ss[(size_t)(iq*64 + bh)*512 + sp*64 + r];
        const float nrm = fmaxf(sqrtf(s), 1e-12f);
        if (iq == 0) scq[r] = temperature[bh & 7] / nrm;
        else         sck[r] = 1.0f / nrm;
    }
    __syncthreads();
    if (tid < 64) {
        const int d = tid;
        const float qsc = scq[d];
        float mx = -1e30f;
        #pragma unroll 8
        for (int e = 0; e < 64; e++) {
            const float v = S[d*PAD2 + e] * qsc * sck[e];
            S[d*PAD2 + e] = v;
            mx = fmaxf(mx, v);
        }
        float sm = 0.0f;
        #pragma unroll 8
        for (int e = 0; e < 64; e++) {
            const float ex = __expf(S[d*PAD2 + e] - mx);
            S[d*PAD2 + e] = ex;
            sm += ex;
        }
        const float inv = 1.0f / sm;
        #pragma unroll 8
        for (int e = 0; e < 64; e++)
            g_attn[(size_t)bh*4096 + d*64 + e] = S[d*PAD2 + e] * inv;
    }
}

// ===========================================================================
// K4c: out[d][n] = sum_e attn[d][e] v[e][n]; gelu; write g_y [b,n,c] (tf32-rounded).
// ===========================================================================
__global__ void __launch_bounds__(256) attn_v_kernel() {
    __shared__ float attn[64*PAD];
    __shared__ float vs[64*PAD];
    const int bh = blockIdx.x;
    const int b = bh >> 3, h = bh & 7;
    const int n0 = blockIdx.y * 64;
    const float* __restrict__ v = g_qkv + (size_t)(2*64 + bh) * 64 * 4096;
    const int tid = threadIdx.x;
    const int tx = tid & 15, ty = tid >> 4;

    for (int idx = tid; idx < 4096; idx += 256)
        attn[(idx >> 6)*PAD + (idx & 63)] = g_attn[(size_t)bh*4096 + idx];
    #pragma unroll
    for (int j = 0; j < 4; j++) {
        const int r = j*16 + ty;
        const int c = tx*4;
        const float4 vv = *(const float4*)(v + (size_t)r*4096 + n0 + c);
        *(float4*)&vs[r*PAD + c] = vv;
    }
    __syncthreads();

    float acc[4][4];
    #pragma unroll
    for (int i = 0; i < 4; i++)
        #pragma unroll
        for (int j = 0; j < 4; j++) acc[i][j] = 0.0f;
    #pragma unroll 4
    for (int e0 = 0; e0 < 64; e0 += 4) {
        float4 a4[4], v4[4];
        #pragma unroll
        for (int j = 0; j < 4; j++) a4[j] = *(const float4*)&attn[(tx*4+j)*PAD + e0];
        #pragma unroll
        for (int qq = 0; qq < 4; qq++) v4[qq] = *(const float4*)&vs[(e0+qq)*PAD + ty*4];
        #pragma unroll
        for (int j = 0; j < 4; j++) {
            const float a0 = a4[j].x, a1 = a4[j].y, a2 = a4[j].z, a3 = a4[j].w;
            #pragma unroll
            for (int i = 0; i < 4; i++) {
                const float* vp0 = (const float*)&v4[0];
                const float* vp1 = (const float*)&v4[1];
                const float* vp2 = (const float*)&v4[2];
                const float* vp3 = (const float*)&v4[3];
                acc[i][j] = fmaf(a0, vp0[i], acc[i][j]);
                acc[i][j] = fmaf(a1, vp1[i], acc[i][j]);
                acc[i][j] = fmaf(a2, vp2[i], acc[i][j]);
                acc[i][j] = fmaf(a3, vp3[i], acc[i][j]);
            }
        }
    }
    #pragma unroll
    for (int i = 0; i < 4; i++) {
        const int n = n0 + ty*4 + i;
        const size_t t = (size_t)b*4096 + n;
        float4 o;
        float xg;
        xg = acc[i][0]; o.x = tf32r(0.5f*xg*(1.0f + erff(xg*0.70710678118654752f)));
        xg = acc[i][1]; o.y = tf32r(0.5f*xg*(1.0f + erff(xg*0.70710678118654752f)));
        xg = acc[i][2]; o.z = tf32r(0.5f*xg*(1.0f + erff(xg*0.70710678118654752f)));
        xg = acc[i][3]; o.w = tf32r(0.5f*xg*(1.0f + erff(xg*0.70710678118654752f)));
        *(float4*)(g_y + t*512 + h*64 + tx*4) = o;
    }
}

// ===========================================================================
extern "C" void kernel_launch(void* const* d_in, const int* in_sizes, int n_in,
                              void* d_out, int out_size) {
    const float* x           = (const float*)d_in[0];
    const float* ln_g        = (const float*)d_in[1];
    const float* ln_b        = (const float*)d_in[2];
    const float* qkv_w       = (const float*)d_in[3];
    const float* temperature = (const float*)d_in[4];
    const float* proj_w      = (const float*)d_in[5];
    const float* proj_b      = (const float*)d_in[6];
    float* out = (float*)d_out;

    cudaFuncSetAttribute(mmagemm<0>, cudaFuncAttributeMaxDynamicSharedMemorySize, GEMM_SMEM);
    cudaFuncSetAttribute(mmagemm<1>, cudaFuncAttributeMaxDynamicSharedMemorySize, GEMM_SMEM);

    round_w_kernel<<<512, 256>>>(qkv_w, proj_w);
    ln_kernel<<<Tt, 128>>>(x, ln_g, ln_b);
    mmagemm<0><<<dim3(1536/256, Tt/128), 256, GEMM_SMEM>>>(nullptr, nullptr);
    attn_qk_kernel<<<dim3(64, 8), 256>>>();
    softmax_kernel<<<64, 256>>>(temperature);
    attn_v_kernel<<<dim3(64, 64), 256>>>();
    mmagemm<1><<<dim3(512/256, Tt/128), 256, GEMM_SMEM>>>(proj_b, out);
}

// round 7
// speedup vs baseline: 1.1680x; 1.1680x over previous
#include <cuda_runtime.h>
#include <math.h>
#include <stdint.h>

#define Bb 8
#define Nn 4096
#define Cc 512
#define Hh 8
#define DHd 64
#define Tt (Bb*Nn)   // 32768 tokens
#define NSPLIT 16

// Scratch (allocation-free rule: device globals)
__device__ float g_xn[Tt*Cc];                 // LayerNorm output [T,C], tf32-rounded
__device__ float g_qkv[3*Bb*Hh*DHd*Nn];       // [i][b][h][d][n] fp32 (UNnormalized q,k)
__device__ float g_y[Tt*Cc];                  // gelu(attn@v) [T,C], tf32-rounded
__device__ float g_Sp[64*NSPLIT*64*64];       // partial raw S per (bh, split)
__device__ float g_ss[2*64*NSPLIT*64];        // partial sum-of-squares [iq][bh][split][row]
__device__ float g_attn[64*64*64];            // softmaxed attn [bh][d][e]
__device__ float g_wq[1536*512];              // tf32-rounded qkv_w
__device__ float g_wp[512*512];               // tf32-rounded proj_w

__device__ __forceinline__ uint32_t smem_u32(const void* p) {
    uint32_t a;
    asm("{ .reg .u64 t; cvta.to.shared.u64 t, %1; cvt.u32.u64 %0, t; }"
        : "=r"(a) : "l"(p));
    return a;
}
__device__ __forceinline__ float tf32r(float f) {
    uint32_t u;
    asm("cvt.rna.tf32.f32 %0, %1;" : "=r"(u) : "f"(f));
    return __uint_as_float(u);
}
__device__ __forceinline__ void cp16(uint32_t daddr, const float* src) {
    asm volatile("{ .reg .u64 p; cvta.to.global.u64 p, %1;"
                 "  cp.async.cg.shared.global [%0], [p], 16; }"
                 :: "r"(daddr), "l"(src) : "memory");
}

// ===========================================================================
// K0: round weights to tf32 representable values (rna)
// ===========================================================================
__global__ void round_w_kernel(const float* __restrict__ qkv_w,
                               const float* __restrict__ proj_w) {
    const int n1 = 1536*512/4, n2 = 512*512/4;
    for (int i = blockIdx.x*blockDim.x + threadIdx.x; i < n1 + n2;
         i += gridDim.x*blockDim.x) {
        const float4 v = (i < n1) ? ((const float4*)qkv_w)[i]
                                  : ((const float4*)proj_w)[i - n1];
        float4 o;
        o.x = tf32r(v.x); o.y = tf32r(v.y); o.z = tf32r(v.z); o.w = tf32r(v.w);
        if (i < n1) ((float4*)g_wq)[i] = o;
        else        ((float4*)g_wp)[i - n1] = o;
    }
}

// ===========================================================================
// K1: LayerNorm (outputs tf32-rounded)
// ===========================================================================
__global__ void ln_kernel(const float* __restrict__ x,
                          const float* __restrict__ gam,
                          const float* __restrict__ bet) {
    const int t = blockIdx.x;
    const int tid = threadIdx.x;           // 128
    const float4 xv = *(const float4*)(x + (size_t)t*Cc + tid*4);
    float s  = xv.x + xv.y + xv.z + xv.w;
    float ss = xv.x*xv.x + xv.y*xv.y + xv.z*xv.z + xv.w*xv.w;
    #pragma unroll
    for (int o = 16; o > 0; o >>= 1) {
        s  += __shfl_xor_sync(0xffffffffu, s,  o);
        ss += __shfl_xor_sync(0xffffffffu, ss, o);
    }
    __shared__ float shs[4], shss[4];
    const int w = tid >> 5, l = tid & 31;
    if (l == 0) { shs[w] = s; shss[w] = ss; }
    __syncthreads();
    const float tot  = shs[0]  + shs[1]  + shs[2]  + shs[3];
    const float tots = shss[0] + shss[1] + shss[2] + shss[3];
    const float mean = tot * (1.0f/512.0f);
    const float var  = tots * (1.0f/512.0f) - mean*mean;
    const float inv  = rsqrtf(var + 1e-5f);
    const float4 gv = *(const float4*)(gam + tid*4);
    const float4 bv = *(const float4*)(bet + tid*4);
    float4 o;
    o.x = tf32r((xv.x - mean)*inv*gv.x + bv.x);
    o.y = tf32r((xv.y - mean)*inv*gv.y + bv.y);
    o.z = tf32r((xv.z - mean)*inv*gv.z + bv.z);
    o.w = tf32r((xv.w - mean)*inv*gv.w + bv.w);
    *(float4*)(g_xn + (size_t)t*Cc + tid*4) = o;
}

// ===========================================================================
// tf32 mma.sync GEMM: C[t,o] = sum_c A[t,c]*W[o,c].
// Block 128(m) x 256(n), 256 thr (8 warps, 2x4), warp tile 64x64.
// Smem [m][k] ld=36 words, cp.async 3-stage pipeline, ldmatrix frag loads.
// EPI=0: A=g_xn, W=g_wq -> scatter g_qkv.  EPI=1: A=g_y, W=g_wp -> out+bias.
// ===========================================================================
#define LDK 36
#define A_BYTES (128*LDK*4)      // 18432
#define W_BYTES (256*LDK*4)      // 36864
#define BUF_BYTES (A_BYTES + W_BYTES)  // 55296
#define GEMM_SMEM (3*BUF_BYTES)        // 165888

template<int EPI>
__global__ void __launch_bounds__(256, 1) mmagemm(const float* __restrict__ bias,
                                                  float* __restrict__ out) {
    extern __shared__ float smem[];
    const uint32_t sb = smem_u32(smem);
    const float* __restrict__ A = (EPI == 0) ? g_xn : g_y;
    const float* __restrict__ W = (EPI == 0) ? g_wq : g_wp;
    const int tid = threadIdx.x;
    const int wid = tid >> 5, lane = tid & 31;
    const int t0 = blockIdx.y * 128;
    const int o0 = blockIdx.x * 256;
    const int wm = wid >> 2, wn = wid & 3;
    const int g = lane >> 2, tg = lane & 3;

    // staging mapping
    int ra[4], ca[4], rw[8], cw[8];
    #pragma unroll
    for (int j = 0; j < 4; j++) { const int idx = j*256 + tid; ra[j] = idx >> 3; ca[j] = (idx & 7)*4; }
    #pragma unroll
    for (int j = 0; j < 8; j++) { const int idx = j*256 + tid; rw[j] = idx >> 3; cw[j] = (idx & 7)*4; }

    // ldmatrix lane base addresses
    const int l15 = lane & 15;
    const uint32_t baseA = sb + (uint32_t)(((wm*64 + l15)*LDK + ((lane & 16) ? 4 : 0)) * 4);
    const int l7 = lane & 7;
    const uint32_t baseB = sb + A_BYTES + (uint32_t)(((wn*64 + l7)*LDK + ((lane & 8) ? 4 : 0)) * 4);

    float acc[4][8][4];
    #pragma unroll
    for (int mt = 0; mt < 4; mt++)
        #pragma unroll
        for (int nt = 0; nt < 8; nt++)
            #pragma unroll
            for (int r = 0; r < 4; r++) acc[mt][nt][r] = 0.0f;

    // prologue: stage tiles 0,1 into buffers 0,1
    #pragma unroll
    for (int s = 0; s < 2; s++) {
        const uint32_t sA = sb + s*BUF_BYTES, sW = sA + A_BYTES;
        const int k0 = s * 32;
        #pragma unroll
        for (int j = 0; j < 4; j++)
            cp16(sA + (ra[j]*LDK + ca[j])*4, A + (size_t)(t0 + ra[j])*512 + k0 + ca[j]);
        #pragma unroll
        for (int j = 0; j < 8; j++)
            cp16(sW + (rw[j]*LDK + cw[j])*4, W + (size_t)(o0 + rw[j])*512 + k0 + cw[j]);
        asm volatile("cp.async.commit_group;" ::: "memory");
    }

    for (int c = 0; c < 16; c++) {
        if (c < 15) asm volatile("cp.async.wait_group 1;" ::: "memory");
        else        asm volatile("cp.async.wait_group 0;" ::: "memory");
        __syncthreads();
        if (c + 2 < 16) {
            const int k0 = (c + 2) * 32;
            const uint32_t sA = sb + ((c + 2) % 3)*BUF_BYTES;
            const uint32_t sW = sA + A_BYTES;
            #pragma unroll
            for (int j = 0; j < 4; j++)
                cp16(sA + (ra[j]*LDK + ca[j])*4, A + (size_t)(t0 + ra[j])*512 + k0 + ca[j]);
            #pragma unroll
            for (int j = 0; j < 8; j++)
                cp16(sW + (rw[j]*LDK + cw[j])*4, W + (size_t)(o0 + rw[j])*512 + k0 + cw[j]);
            asm volatile("cp.async.commit_group;" ::: "memory");
        }
        const uint32_t aoff = baseA + (c % 3)*BUF_BYTES;
        const uint32_t boff = baseB + (c % 3)*BUF_BYTES;
        #pragma unroll
        for (int ks = 0; ks < 4; ks++) {
            uint32_t a[4][4], b[8][2];
            #pragma unroll
            for (int mt = 0; mt < 4; mt++) {
                const uint32_t ad = aoff + (uint32_t)((mt*16*LDK + ks*8) * 4);
                asm volatile("ldmatrix.sync.aligned.m8n8.x4.shared.b16 {%0,%1,%2,%3}, [%4];"
                    : "=r"(a[mt][0]), "=r"(a[mt][1]), "=r"(a[mt][2]), "=r"(a[mt][3]) : "r"(ad));
            }
            #pragma unroll
            for (int nt = 0; nt < 8; nt++) {
                const uint32_t bd = boff + (uint32_t)((nt*8*LDK + ks*8) * 4);
                asm volatile("ldmatrix.sync.aligned.m8n8.x2.shared.b16 {%0,%1}, [%2];"
                    : "=r"(b[nt][0]), "=r"(b[nt][1]) : "r"(bd));
            }
            #pragma unroll
            for (int mt = 0; mt < 4; mt++)
                #pragma unroll
                for (int nt = 0; nt < 8; nt++) {
                    asm volatile(
                        "mma.sync.aligned.m16n8k8.row.col.f32.tf32.tf32.f32 "
                        "{%0,%1,%2,%3}, {%4,%5,%6,%7}, {%8,%9}, {%0,%1,%2,%3};"
                        : "+f"(acc[mt][nt][0]), "+f"(acc[mt][nt][1]),
                          "+f"(acc[mt][nt][2]), "+f"(acc[mt][nt][3])
                        : "r"(a[mt][0]), "r"(a[mt][1]), "r"(a[mt][2]), "r"(a[mt][3]),
                          "r"(b[nt][0]), "r"(b[nt][1]));
                }
        }
    }

    // ---- epilogue (direct global stores) ----
    const int m0g = t0 + wm*64;
    const int o0g = o0 + wn*64;
    if (EPI == 0) {
        const int i_ = o0g >> 9;
        const int h  = (o0g >> 6) & 7;
        const int b  = m0g >> 12;                 // whole block same batch
        const int rowbase = ((i_*8 + b)*8 + h) * 64;
        #pragma unroll
        for (int mt = 0; mt < 4; mt++) {
            const int t1 = m0g + mt*16 + g;
            const int n1 = t1 & 4095;
            #pragma unroll
            for (int nt = 0; nt < 8; nt++) {
                const int row = rowbase + nt*8 + tg*2;
                g_qkv[(size_t)row*4096 + n1]            = acc[mt][nt][0];
                g_qkv[(size_t)(row + 1)*4096 + n1]      = acc[mt][nt][1];
                g_qkv[(size_t)row*4096 + n1 + 8]        = acc[mt][nt][2];
                g_qkv[(size_t)(row + 1)*4096 + n1 + 8]  = acc[mt][nt][3];
            }
        }
    } else {
        #pragma unroll
        for (int mt = 0; mt < 4; mt++) {
            const int t1 = m0g + mt*16 + g;
            #pragma unroll
            for (int nt = 0; nt < 8; nt++) {
                const int o = o0g + nt*8 + tg*2;
                const float b0 = bias[o], b1 = bias[o + 1];
                float2 v0; v0.x = acc[mt][nt][0] + b0; v0.y = acc[mt][nt][1] + b1;
                float2 v1; v1.x = acc[mt][nt][2] + b0; v1.y = acc[mt][nt][3] + b1;
                *(float2*)(out + (size_t)t1*512 + o)       = v0;
                *(float2*)(out + (size_t)(t1 + 8)*512 + o) = v1;
            }
        }
    }
}

// ===========================================================================
// K4a: raw partial S = q k^T over a 256-token slice + per-row sum-of-squares
// partials for q and k. grid (64 bh, NSPLIT), 256 thr. Scalar-LDS inner loop
// (PAD=65: lane stride 4*65 = 260 ≡ 4 mod 32 banks -> conflict-free).
// Smem stores are scalar (PAD=65 rows are not 16B-aligned).
// ===========================================================================
#define PAD 65
__global__ void __launch_bounds__(256) attn_qk_kernel() {
    __shared__ float qs[64*PAD];
    __shared__ float ks[64*PAD];
    const int bh = blockIdx.x;
    const int split = blockIdx.y;
    const float* __restrict__ q = g_qkv + (size_t)bh * 64 * 4096;
    const float* __restrict__ k = g_qkv + (size_t)(64 + bh) * 64 * 4096;
    const int tid = threadIdx.x;
    const int tx = tid & 15, ty = tid >> 4;

    float S[4][4];
    #pragma unroll
    for (int i = 0; i < 4; i++)
        #pragma unroll
        for (int j = 0; j < 4; j++) S[i][j] = 0.0f;
    float ssq[4] = {0,0,0,0}, ssk[4] = {0,0,0,0};

    const int nbeg = split * (4096/NSPLIT);
    for (int n0 = nbeg; n0 < nbeg + 4096/NSPLIT; n0 += 64) {
        #pragma unroll
        for (int j = 0; j < 4; j++) {
            const int r = j*16 + ty;
            const int c = tx*4;
            const float4 qv = *(const float4*)(q + (size_t)r*4096 + n0 + c);
            qs[r*PAD + c+0] = qv.x; qs[r*PAD + c+1] = qv.y;
            qs[r*PAD + c+2] = qv.z; qs[r*PAD + c+3] = qv.w;
            ssq[j] += qv.x*qv.x + qv.y*qv.y + qv.z*qv.z + qv.w*qv.w;
            const float4 kv = *(const float4*)(k + (size_t)r*4096 + n0 + c);
            ks[r*PAD + c+0] = kv.x; ks[r*PAD + c+1] = kv.y;
            ks[r*PAD + c+2] = kv.z; ks[r*PAD + c+3] = kv.w;
            ssk[j] += kv.x*kv.x + kv.y*kv.y + kv.z*kv.z + kv.w*kv.w;
        }
        __syncthreads();
        #pragma unroll 8
        for (int n = 0; n < 64; n++) {
            float qr[4], kr[4];
            #pragma unroll
            for (int i = 0; i < 4; i++) qr[i] = qs[(ty*4+i)*PAD + n];
            #pragma unroll
            for (int j = 0; j < 4; j++) kr[j] = ks[(tx*4+j)*PAD + n];
            #pragma unroll
            for (int i = 0; i < 4; i++)
                #pragma unroll
                for (int j = 0; j < 4; j++)
                    S[i][j] = fmaf(qr[i], kr[j], S[i][j]);
        }
        __syncthreads();
    }
    // reduce ss over the 16 lanes sharing each row group
    #pragma unroll
    for (int o = 1; o < 16; o <<= 1) {
        #pragma unroll
        for (int j = 0; j < 4; j++) {
            ssq[j] += __shfl_xor_sync(0xffffffffu, ssq[j], o);
            ssk[j] += __shfl_xor_sync(0xffffffffu, ssk[j], o);
        }
    }
    if (tx == 0) {
        #pragma unroll
        for (int j = 0; j < 4; j++) {
            const int r = j*16 + ty;
            g_ss[((size_t)bh*NSPLIT + split)*64 + r]              = ssq[j];
            g_ss[((size_t)(64 + bh)*NSPLIT + split)*64 + r]       = ssk[j];
        }
    }
    float* dst = g_Sp + ((size_t)(bh*NSPLIT + split)) * 4096;
    #pragma unroll
    for (int i = 0; i < 4; i++) {
        float4 v;
        v.x = S[i][0]; v.y = S[i][1]; v.z = S[i][2]; v.w = S[i][3];
        *(float4*)(dst + (ty*4+i)*64 + tx*4) = v;
    }
}

// ===========================================================================
// K4b: reduce NSPLIT partials, apply norm scales * temperature, softmax over e.
// ===========================================================================
__global__ void __launch_bounds__(256) softmax_kernel(const float* __restrict__ temperature) {
    __shared__ float S[64*PAD];
    __shared__ float scq[64], sck[64];
    const int bh = blockIdx.x;
    const int tid = threadIdx.x;
    for (int idx = tid; idx < 4096; idx += 256) {
        float s = 0.0f;
        #pragma unroll
        for (int sp = 0; sp < NSPLIT; sp++)
            s += g_Sp[((size_t)(bh*NSPLIT + sp))*4096 + idx];
        S[(idx >> 6)*PAD + (idx & 63)] = s;
    }
    if (tid < 128) {
        const int iq = tid >> 6;          // 0=q, 1=k
        const int r = tid & 63;
        float s = 0.0f;
        #pragma unroll
        for (int sp = 0; sp < NSPLIT; sp++)
            s += g_ss[((size_t)(iq*64 + bh)*NSPLIT + sp)*64 + r];
        const float nrm = fmaxf(sqrtf(s), 1e-12f);
        if (iq == 0) scq[r] = temperature[bh & 7] / nrm;
        else         sck[r] = 1.0f / nrm;
    }
    __syncthreads();
    if (tid < 64) {
        const int d = tid;
        const float qsc = scq[d];
        float mx = -1e30f;
        #pragma unroll 8
        for (int e = 0; e < 64; e++) {
            const float v = S[d*PAD + e] * qsc * sck[e];
            S[d*PAD + e] = v;
            mx = fmaxf(mx, v);
        }
        float sm = 0.0f;
        #pragma unroll 8
        for (int e = 0; e < 64; e++) {
            const float ex = __expf(S[d*PAD + e] - mx);
            S[d*PAD + e] = ex;
            sm += ex;
        }
        const float inv = 1.0f / sm;
        #pragma unroll 8
        for (int e = 0; e < 64; e++)
            g_attn[(size_t)bh*4096 + d*64 + e] = S[d*PAD + e] * inv;
    }
}

// ===========================================================================
// K4c: out[d][n] = sum_e attn[d][e] v[e][n]; gelu; write g_y [b,n,c] (tf32-rounded).
// grid (64 bh, 64 n-chunks), 256 thr. Scalar-LDS inner loop, scalar smem stores.
// ===========================================================================
__global__ void __launch_bounds__(256) attn_v_kernel() {
    __shared__ float attn[64*PAD];
    __shared__ float vs[64*PAD];
    const int bh = blockIdx.x;
    const int b = bh >> 3, h = bh & 7;
    const int n0 = blockIdx.y * 64;
    const float* __restrict__ v = g_qkv + (size_t)(2*64 + bh) * 64 * 4096;
    const int tid = threadIdx.x;
    const int tx = tid & 15, ty = tid >> 4;

    for (int idx = tid; idx < 4096; idx += 256)
        attn[(idx >> 6)*PAD + (idx & 63)] = g_attn[(size_t)bh*4096 + idx];
    #pragma unroll
    for (int j = 0; j < 4; j++) {
        const int r = j*16 + ty;
        const int c = tx*4;
        const float4 vv = *(const float4*)(v + (size_t)r*4096 + n0 + c);
        vs[r*PAD + c+0] = vv.x; vs[r*PAD + c+1] = vv.y;
        vs[r*PAD + c+2] = vv.z; vs[r*PAD + c+3] = vv.w;
    }
    __syncthreads();

    float acc[4][4];
    #pragma unroll
    for (int i = 0; i < 4; i++)
        #pragma unroll
        for (int j = 0; j < 4; j++) acc[i][j] = 0.0f;
    #pragma unroll 8
    for (int e = 0; e < 64; e++) {
        float ar[4], vr[4];
        #pragma unroll
        for (int j = 0; j < 4; j++) ar[j] = attn[(tx*4+j)*PAD + e];
        #pragma unroll
        for (int i = 0; i < 4; i++) vr[i] = vs[e*PAD + ty*4 + i];
        #pragma unroll
        for (int i = 0; i < 4; i++)
            #pragma unroll
            for (int j = 0; j < 4; j++)
                acc[i][j] = fmaf(ar[j], vr[i], acc[i][j]);
    }
    #pragma unroll
    for (int i = 0; i < 4; i++) {
        const int n = n0 + ty*4 + i;
        const size_t t = (size_t)b*4096 + n;
        float4 o;
        float xg;
        xg = acc[i][0]; o.x = tf32r(0.5f*xg*(1.0f + erff(xg*0.70710678118654752f)));
        xg = acc[i][1]; o.y = tf32r(0.5f*xg*(1.0f + erff(xg*0.70710678118654752f)));
        xg = acc[i][2]; o.z = tf32r(0.5f*xg*(1.0f + erff(xg*0.70710678118654752f)));
        xg = acc[i][3]; o.w = tf32r(0.5f*xg*(1.0f + erff(xg*0.70710678118654752f)));
        *(float4*)(g_y + t*512 + h*64 + tx*4) = o;
    }
}

// ===========================================================================
extern "C" void kernel_launch(void* const* d_in, const int* in_sizes, int n_in,
                              void* d_out, int out_size) {
    const float* x           = (const float*)d_in[0];
    const float* ln_g        = (const float*)d_in[1];
    const float* ln_b        = (const float*)d_in[2];
    const float* qkv_w       = (const float*)d_in[3];
    const float* temperature = (const float*)d_in[4];
    const float* proj_w      = (const float*)d_in[5];
    const float* proj_b      = (const float*)d_in[6];
    float* out = (float*)d_out;

    cudaFuncSetAttribute(mmagemm<0>, cudaFuncAttributeMaxDynamicSharedMemorySize, GEMM_SMEM);
    cudaFuncSetAttribute(mmagemm<1>, cudaFuncAttributeMaxDynamicSharedMemorySize, GEMM_SMEM);

    round_w_kernel<<<512, 256>>>(qkv_w, proj_w);
    ln_kernel<<<Tt, 128>>>(x, ln_g, ln_b);
    mmagemm<0><<<dim3(1536/256, Tt/128), 256, GEMM_SMEM>>>(nullptr, nullptr);
    attn_qk_kernel<<<dim3(64, NSPLIT), 256>>>();
    softmax_kernel<<<64, 256>>>(temperature);
    attn_v_kernel<<<dim3(64, 64), 256>>>();
    mmagemm<1><<<dim3(512/256, Tt/128), 256, GEMM_SMEM>>>(proj_b, out);
}

// round 8
// speedup vs baseline: 1.3332x; 1.1415x over previous
#include <cuda_runtime.h>
#include <math.h>
#include <stdint.h>

#define Bb 8
#define Nn 4096
#define Cc 512
#define Hh 8
#define DHd 64
#define Tt (Bb*Nn)   // 32768 tokens
#define NSPLIT 16

// Scratch (allocation-free rule: device globals)
__device__ float g_xn[Tt*Cc];                 // LayerNorm output [T,C], tf32-rounded
__device__ float g_qkv[3*Bb*Hh*DHd*Nn];       // [i][b][h][d][n], tf32-rounded
__device__ float g_y[Tt*Cc];                  // gelu(attn@v) [T,C], tf32-rounded
__device__ float g_Sp[64*NSPLIT*64*64];       // partial raw S per (bh, split)
__device__ float g_ss[2*64*NSPLIT*64];        // partial sum-of-squares
__device__ float g_attn[64*64*64];            // softmaxed attn [bh][d][e], tf32-rounded
__device__ float g_wq[1536*512];              // tf32-rounded qkv_w
__device__ float g_wp[512*512];               // tf32-rounded proj_w

__device__ __forceinline__ uint32_t smem_u32(const void* p) {
    uint32_t a;
    asm("{ .reg .u64 t; cvta.to.shared.u64 t, %1; cvt.u32.u64 %0, t; }"
        : "=r"(a) : "l"(p));
    return a;
}
__device__ __forceinline__ float tf32r(float f) {
    uint32_t u;
    asm("cvt.rna.tf32.f32 %0, %1;" : "=r"(u) : "f"(f));
    return __uint_as_float(u);
}
__device__ __forceinline__ void cp16(uint32_t daddr, const float* src) {
    asm volatile("{ .reg .u64 p; cvta.to.global.u64 p, %1;"
                 "  cp.async.cg.shared.global [%0], [p], 16; }"
                 :: "r"(daddr), "l"(src) : "memory");
}
#define LDM_X4(a0,a1,a2,a3,addr) \
    asm volatile("ldmatrix.sync.aligned.m8n8.x4.shared.b16 {%0,%1,%2,%3}, [%4];" \
        : "=r"(a0), "=r"(a1), "=r"(a2), "=r"(a3) : "r"(addr))
#define LDM_X2(b0,b1,addr) \
    asm volatile("ldmatrix.sync.aligned.m8n8.x2.shared.b16 {%0,%1}, [%2];" \
        : "=r"(b0), "=r"(b1) : "r"(addr))
#define MMA_TF32(c0,c1,c2,c3,a0,a1,a2,a3,b0,b1) \
    asm volatile("mma.sync.aligned.m16n8k8.row.col.f32.tf32.tf32.f32 " \
        "{%0,%1,%2,%3}, {%4,%5,%6,%7}, {%8,%9}, {%0,%1,%2,%3};" \
        : "+f"(c0), "+f"(c1), "+f"(c2), "+f"(c3) \
        : "r"(a0), "r"(a1), "r"(a2), "r"(a3), "r"(b0), "r"(b1))

// ===========================================================================
// K0: round weights to tf32 representable values (rna)
// ===========================================================================
__global__ void round_w_kernel(const float* __restrict__ qkv_w,
                               const float* __restrict__ proj_w) {
    const int n1 = 1536*512/4, n2 = 512*512/4;
    for (int i = blockIdx.x*blockDim.x + threadIdx.x; i < n1 + n2;
         i += gridDim.x*blockDim.x) {
        const float4 v = (i < n1) ? ((const float4*)qkv_w)[i]
                                  : ((const float4*)proj_w)[i - n1];
        float4 o;
        o.x = tf32r(v.x); o.y = tf32r(v.y); o.z = tf32r(v.z); o.w = tf32r(v.w);
        if (i < n1) ((float4*)g_wq)[i] = o;
        else        ((float4*)g_wp)[i - n1] = o;
    }
}

// ===========================================================================
// K1: LayerNorm (outputs tf32-rounded)
// ===========================================================================
__global__ void ln_kernel(const float* __restrict__ x,
                          const float* __restrict__ gam,
                          const float* __restrict__ bet) {
    const int t = blockIdx.x;
    const int tid = threadIdx.x;           // 128
    const float4 xv = *(const float4*)(x + (size_t)t*Cc + tid*4);
    float s  = xv.x + xv.y + xv.z + xv.w;
    float ss = xv.x*xv.x + xv.y*xv.y + xv.z*xv.z + xv.w*xv.w;
    #pragma unroll
    for (int o = 16; o > 0; o >>= 1) {
        s  += __shfl_xor_sync(0xffffffffu, s,  o);
        ss += __shfl_xor_sync(0xffffffffu, ss, o);
    }
    __shared__ float shs[4], shss[4];
    const int w = tid >> 5, l = tid & 31;
    if (l == 0) { shs[w] = s; shss[w] = ss; }
    __syncthreads();
    const float tot  = shs[0]  + shs[1]  + shs[2]  + shs[3];
    const float tots = shss[0] + shss[1] + shss[2] + shss[3];
    const float mean = tot * (1.0f/512.0f);
    const float var  = tots * (1.0f/512.0f) - mean*mean;
    const float inv  = rsqrtf(var + 1e-5f);
    const float4 gv = *(const float4*)(gam + tid*4);
    const float4 bv = *(const float4*)(bet + tid*4);
    float4 o;
    o.x = tf32r((xv.x - mean)*inv*gv.x + bv.x);
    o.y = tf32r((xv.y - mean)*inv*gv.y + bv.y);
    o.z = tf32r((xv.z - mean)*inv*gv.z + bv.z);
    o.w = tf32r((xv.w - mean)*inv*gv.w + bv.w);
    *(float4*)(g_xn + (size_t)t*Cc + tid*4) = o;
}

// ===========================================================================
// tf32 mma.sync GEMM (unchanged from R7 except EPI=0 rounds outputs)
// ===========================================================================
#define LDK 36
#define A_BYTES (128*LDK*4)
#define W_BYTES (256*LDK*4)
#define BUF_BYTES (A_BYTES + W_BYTES)
#define GEMM_SMEM (3*BUF_BYTES)

template<int EPI>
__global__ void __launch_bounds__(256, 1) mmagemm(const float* __restrict__ bias,
                                                  float* __restrict__ out) {
    extern __shared__ float smem[];
    const uint32_t sb = smem_u32(smem);
    const float* __restrict__ A = (EPI == 0) ? g_xn : g_y;
    const float* __restrict__ W = (EPI == 0) ? g_wq : g_wp;
    const int tid = threadIdx.x;
    const int wid = tid >> 5, lane = tid & 31;
    const int t0 = blockIdx.y * 128;
    const int o0 = blockIdx.x * 256;
    const int wm = wid >> 2, wn = wid & 3;
    const int g = lane >> 2, tg = lane & 3;

    int ra[4], ca[4], rw[8], cw[8];
    #pragma unroll
    for (int j = 0; j < 4; j++) { const int idx = j*256 + tid; ra[j] = idx >> 3; ca[j] = (idx & 7)*4; }
    #pragma unroll
    for (int j = 0; j < 8; j++) { const int idx = j*256 + tid; rw[j] = idx >> 3; cw[j] = (idx & 7)*4; }

    const int l15 = lane & 15;
    const uint32_t baseA = sb + (uint32_t)(((wm*64 + l15)*LDK + ((lane & 16) ? 4 : 0)) * 4);
    const int l7 = lane & 7;
    const uint32_t baseB = sb + A_BYTES + (uint32_t)(((wn*64 + l7)*LDK + ((lane & 8) ? 4 : 0)) * 4);

    float acc[4][8][4];
    #pragma unroll
    for (int mt = 0; mt < 4; mt++)
        #pragma unroll
        for (int nt = 0; nt < 8; nt++)
            #pragma unroll
            for (int r = 0; r < 4; r++) acc[mt][nt][r] = 0.0f;

    #pragma unroll
    for (int s = 0; s < 2; s++) {
        const uint32_t sA = sb + s*BUF_BYTES, sW = sA + A_BYTES;
        const int k0 = s * 32;
        #pragma unroll
        for (int j = 0; j < 4; j++)
            cp16(sA + (ra[j]*LDK + ca[j])*4, A + (size_t)(t0 + ra[j])*512 + k0 + ca[j]);
        #pragma unroll
        for (int j = 0; j < 8; j++)
            cp16(sW + (rw[j]*LDK + cw[j])*4, W + (size_t)(o0 + rw[j])*512 + k0 + cw[j]);
        asm volatile("cp.async.commit_group;" ::: "memory");
    }

    for (int c = 0; c < 16; c++) {
        if (c < 15) asm volatile("cp.async.wait_group 1;" ::: "memory");
        else        asm volatile("cp.async.wait_group 0;" ::: "memory");
        __syncthreads();
        if (c + 2 < 16) {
            const int k0 = (c + 2) * 32;
            const uint32_t sA = sb + ((c + 2) % 3)*BUF_BYTES;
            const uint32_t sW = sA + A_BYTES;
            #pragma unroll
            for (int j = 0; j < 4; j++)
                cp16(sA + (ra[j]*LDK + ca[j])*4, A + (size_t)(t0 + ra[j])*512 + k0 + ca[j]);
            #pragma unroll
            for (int j = 0; j < 8; j++)
                cp16(sW + (rw[j]*LDK + cw[j])*4, W + (size_t)(o0 + rw[j])*512 + k0 + cw[j]);
            asm volatile("cp.async.commit_group;" ::: "memory");
        }
        const uint32_t aoff = baseA + (c % 3)*BUF_BYTES;
        const uint32_t boff = baseB + (c % 3)*BUF_BYTES;
        #pragma unroll
        for (int ks = 0; ks < 4; ks++) {
            uint32_t a[4][4], b[8][2];
            #pragma unroll
            for (int mt = 0; mt < 4; mt++)
                LDM_X4(a[mt][0], a[mt][1], a[mt][2], a[mt][3],
                       aoff + (uint32_t)((mt*16*LDK + ks*8) * 4));
            #pragma unroll
            for (int nt = 0; nt < 8; nt++)
                LDM_X2(b[nt][0], b[nt][1], boff + (uint32_t)((nt*8*LDK + ks*8) * 4));
            #pragma unroll
            for (int mt = 0; mt < 4; mt++)
                #pragma unroll
                for (int nt = 0; nt < 8; nt++)
                    MMA_TF32(acc[mt][nt][0], acc[mt][nt][1], acc[mt][nt][2], acc[mt][nt][3],
                             a[mt][0], a[mt][1], a[mt][2], a[mt][3], b[nt][0], b[nt][1]);
        }
    }

    const int m0g = t0 + wm*64;
    const int o0g = o0 + wn*64;
    if (EPI == 0) {
        const int i_ = o0g >> 9;
        const int h  = (o0g >> 6) & 7;
        const int b  = m0g >> 12;
        const int rowbase = ((i_*8 + b)*8 + h) * 64;
        #pragma unroll
        for (int mt = 0; mt < 4; mt++) {
            const int t1 = m0g + mt*16 + g;
            const int n1 = t1 & 4095;
            #pragma unroll
            for (int nt = 0; nt < 8; nt++) {
                const int row = rowbase + nt*8 + tg*2;
                g_qkv[(size_t)row*4096 + n1]            = tf32r(acc[mt][nt][0]);
                g_qkv[(size_t)(row + 1)*4096 + n1]      = tf32r(acc[mt][nt][1]);
                g_qkv[(size_t)row*4096 + n1 + 8]        = tf32r(acc[mt][nt][2]);
                g_qkv[(size_t)(row + 1)*4096 + n1 + 8]  = tf32r(acc[mt][nt][3]);
            }
        }
    } else {
        #pragma unroll
        for (int mt = 0; mt < 4; mt++) {
            const int t1 = m0g + mt*16 + g;
            #pragma unroll
            for (int nt = 0; nt < 8; nt++) {
                const int o = o0g + nt*8 + tg*2;
                const float b0 = bias[o], b1 = bias[o + 1];
                float2 v0; v0.x = acc[mt][nt][0] + b0; v0.y = acc[mt][nt][1] + b1;
                float2 v1; v1.x = acc[mt][nt][2] + b0; v1.y = acc[mt][nt][3] + b1;
                *(float2*)(out + (size_t)t1*512 + o)       = v0;
                *(float2*)(out + (size_t)(t1 + 8)*512 + o) = v1;
            }
        }
    }
}

// ===========================================================================
// K4a: tf32 mma S-partials: per (bh, split) a 64x64x256 GEMM. 128 thr, 4 warps.
// Each warp: m-rows wid*16..+15, all 64 e-cols (8 n-tiles). Also accumulates
// per-row sum-of-squares partials for q and k during staging.
// ===========================================================================
#define QLDK 36
__global__ void __launch_bounds__(128) attn_qk_mma() {
    __shared__ float qs[64*QLDK];
    __shared__ float ks_[64*QLDK];
    const int bh = blockIdx.x;
    const int split = blockIdx.y;
    const float* __restrict__ q = g_qkv + (size_t)bh * 64 * 4096;
    const float* __restrict__ k = g_qkv + (size_t)(64 + bh) * 64 * 4096;
    const int tid = threadIdx.x;
    const int wid = tid >> 5, lane = tid & 31;
    const uint32_t sq = smem_u32(qs), sk = smem_u32(ks_);
    const int rr = tid >> 3;              // 0..15
    const int cc = (tid & 7) * 4;         // 0..28

    const uint32_t aoff = sq + (uint32_t)(((wid*16 + (lane & 15))*QLDK + ((lane & 16) ? 4 : 0)) * 4);
    const uint32_t boff = sk + (uint32_t)(((lane & 7)*QLDK + ((lane & 8) ? 4 : 0)) * 4);

    float acc[8][4];
    #pragma unroll
    for (int nt = 0; nt < 8; nt++)
        #pragma unroll
        for (int r = 0; r < 4; r++) acc[nt][r] = 0.0f;
    float ssq[4] = {0,0,0,0}, ssk[4] = {0,0,0,0};

    for (int ch = 0; ch < 8; ch++) {
        const int n0 = split*256 + ch*32;
        #pragma unroll
        for (int j = 0; j < 4; j++) {
            const int row = j*16 + rr;
            const float4 qv = *(const float4*)(q + (size_t)row*4096 + n0 + cc);
            *(float4*)&qs[row*QLDK + cc] = qv;
            ssq[j] += qv.x*qv.x + qv.y*qv.y + qv.z*qv.z + qv.w*qv.w;
            const float4 kv = *(const float4*)(k + (size_t)row*4096 + n0 + cc);
            *(float4*)&ks_[row*QLDK + cc] = kv;
            ssk[j] += kv.x*kv.x + kv.y*kv.y + kv.z*kv.z + kv.w*kv.w;
        }
        __syncthreads();
        #pragma unroll
        for (int ks = 0; ks < 4; ks++) {
            uint32_t a[4], b[8][2];
            LDM_X4(a[0], a[1], a[2], a[3], aoff + (uint32_t)((ks*8) * 4));
            #pragma unroll
            for (int nt = 0; nt < 8; nt++)
                LDM_X2(b[nt][0], b[nt][1], boff + (uint32_t)((nt*8*QLDK + ks*8) * 4));
            #pragma unroll
            for (int nt = 0; nt < 8; nt++)
                MMA_TF32(acc[nt][0], acc[nt][1], acc[nt][2], acc[nt][3],
                         a[0], a[1], a[2], a[3], b[nt][0], b[nt][1]);
        }
        __syncthreads();
    }
    // reduce ss over the 8 lanes covering each row
    #pragma unroll
    for (int o = 1; o < 8; o <<= 1) {
        #pragma unroll
        for (int j = 0; j < 4; j++) {
            ssq[j] += __shfl_xor_sync(0xffffffffu, ssq[j], o);
            ssk[j] += __shfl_xor_sync(0xffffffffu, ssk[j], o);
        }
    }
    if ((tid & 7) == 0) {
        #pragma unroll
        for (int j = 0; j < 4; j++) {
            const int row = j*16 + rr;
            g_ss[((size_t)bh*NSPLIT + split)*64 + row]        = ssq[j];
            g_ss[((size_t)(64 + bh)*NSPLIT + split)*64 + row] = ssk[j];
        }
    }
    // write partial S (float2, standard m16n8 C layout)
    float* dst = g_Sp + ((size_t)(bh*NSPLIT + split)) * 4096;
    const int g = lane >> 2, tg = lane & 3;
    const int d0 = wid*16 + g;
    #pragma unroll
    for (int nt = 0; nt < 8; nt++) {
        const int e = nt*8 + tg*2;
        float2 v0; v0.x = acc[nt][0]; v0.y = acc[nt][1];
        float2 v1; v1.x = acc[nt][2]; v1.y = acc[nt][3];
        *(float2*)(dst + d0*64 + e)       = v0;
        *(float2*)(dst + (d0 + 8)*64 + e) = v1;
    }
}

// ===========================================================================
// K4b: reduce NSPLIT partials, apply norm scales * temperature, softmax over e.
// Output tf32-rounded.
// ===========================================================================
#define PAD 65
__global__ void __launch_bounds__(256) softmax_kernel(const float* __restrict__ temperature) {
    __shared__ float S[64*PAD];
    __shared__ float scq[64], sck[64];
    const int bh = blockIdx.x;
    const int tid = threadIdx.x;
    for (int idx = tid; idx < 4096; idx += 256) {
        float s = 0.0f;
        #pragma unroll
        for (int sp = 0; sp < NSPLIT; sp++)
            s += g_Sp[((size_t)(bh*NSPLIT + sp))*4096 + idx];
        S[(idx >> 6)*PAD + (idx & 63)] = s;
    }
    if (tid < 128) {
        const int iq = tid >> 6;
        const int r = tid & 63;
        float s = 0.0f;
        #pragma unroll
        for (int sp = 0; sp < NSPLIT; sp++)
            s += g_ss[((size_t)(iq*64 + bh)*NSPLIT + sp)*64 + r];
        const float nrm = fmaxf(sqrtf(s), 1e-12f);
        if (iq == 0) scq[r] = temperature[bh & 7] / nrm;
        else         sck[r] = 1.0f / nrm;
    }
    __syncthreads();
    if (tid < 64) {
        const int d = tid;
        const float qsc = scq[d];
        float mx = -1e30f;
        #pragma unroll 8
        for (int e = 0; e < 64; e++) {
            const float v = S[d*PAD + e] * qsc * sck[e];
            S[d*PAD + e] = v;
            mx = fmaxf(mx, v);
        }
        float sm = 0.0f;
        #pragma unroll 8
        for (int e = 0; e < 64; e++) {
            const float ex = __expf(S[d*PAD + e] - mx);
            S[d*PAD + e] = ex;
            sm += ex;
        }
        const float inv = 1.0f / sm;
        #pragma unroll 8
        for (int e = 0; e < 64; e++)
            g_attn[(size_t)bh*4096 + d*64 + e] = tf32r(S[d*PAD + e] * inv);
    }
}

// ===========================================================================
// K4c: tf32 mma attn@v + GELU. Per (bh, n-chunk of 128): 64x128x64 GEMM.
// 256 thr, 8 warps (4x2): warp tile 16(m) x 64(n). B = v^T staged in smem.
// ===========================================================================
#define VLDA 68
#define AV_SMEM ((64*VLDA + 128*VLDA)*4)   // 52224 bytes
__global__ void __launch_bounds__(256) attn_v_mma() {
    extern __shared__ float avs[];
    float* As = avs;                 // attn [d][e], 64 x VLDA
    float* Bs = avs + 64*VLDA;       // v^T  [n][e], 128 x VLDA
    const int bh = blockIdx.x;
    const int b = bh >> 3, h = bh & 7;
    const int n0 = blockIdx.y * 128;
    const float* __restrict__ v = g_qkv + (size_t)(128 + bh) * 64 * 4096;
    const int tid = threadIdx.x;
    const int wid = tid >> 5, lane = tid & 31;
    const int wm = wid >> 1, wn = wid & 1;

    // stage attn (4096 floats, float4)
    #pragma unroll
    for (int j = 0; j < 4; j++) {
        const int idx4 = j*256 + tid;
        const int d = idx4 >> 4;
        const int e4 = (idx4 & 15) * 4;
        *(float4*)&As[d*VLDA + e4] = *(const float4*)(g_attn + (size_t)bh*4096 + idx4*4);
    }
    // stage v transposed: load v[e][n] float4 along n, scatter to Bs[n][e]
    #pragma unroll
    for (int j = 0; j < 8; j++) {
        const int idx = j*256 + tid;           // 0..2047
        const int e = idx >> 5;                // 0..63
        const int n4 = (idx & 31) * 4;         // 0..124
        const float4 vv = *(const float4*)(v + (size_t)e*4096 + n0 + n4);
        Bs[(n4+0)*VLDA + e] = vv.x;
        Bs[(n4+1)*VLDA + e] = vv.y;
        Bs[(n4+2)*VLDA + e] = vv.z;
        Bs[(n4+3)*VLDA + e] = vv.w;
    }
    __syncthreads();

    const uint32_t sa = smem_u32(As), sbv = smem_u32(Bs);
    const uint32_t aoff = sa + (uint32_t)(((wm*16 + (lane & 15))*VLDA + ((lane & 16) ? 4 : 0)) * 4);
    const uint32_t boff = sbv + (uint32_t)(((wn*64 + (lane & 7))*VLDA + ((lane & 8) ? 4 : 0)) * 4);

    float acc[8][4];
    #pragma unroll
    for (int nt = 0; nt < 8; nt++)
        #pragma unroll
        for (int r = 0; r < 4; r++) acc[nt][r] = 0.0f;

    #pragma unroll
    for (int ks = 0; ks < 8; ks++) {
        uint32_t a[4], bfr[8][2];
        LDM_X4(a[0], a[1], a[2], a[3], aoff + (uint32_t)((ks*8) * 4));
        #pragma unroll
        for (int nt = 0; nt < 8; nt++)
            LDM_X2(bfr[nt][0], bfr[nt][1], boff + (uint32_t)((nt*8*VLDA + ks*8) * 4));
        #pragma unroll
        for (int nt = 0; nt < 8; nt++)
            MMA_TF32(acc[nt][0], acc[nt][1], acc[nt][2], acc[nt][3],
                     a[0], a[1], a[2], a[3], bfr[nt][0], bfr[nt][1]);
    }

    // epilogue: gelu + scatter to g_y [b,n,c] (c = h*64 + d)
    const int g = lane >> 2, tg = lane & 3;
    const int d0 = wm*16 + g;
    #pragma unroll
    for (int nt = 0; nt < 8; nt++) {
        const int n = n0 + wn*64 + nt*8 + tg*2;
        const size_t t0r = (size_t)b*4096 + n;
        #pragma unroll
        for (int r = 0; r < 4; r++) {
            const int d = d0 + (r >> 1)*8;
            const size_t t = t0r + (r & 1);
            const float xg = acc[nt][r];
            g_y[t*512 + h*64 + d] = tf32r(0.5f*xg*(1.0f + erff(xg*0.70710678118654752f)));
        }
    }
}

// ===========================================================================
extern "C" void kernel_launch(void* const* d_in, const int* in_sizes, int n_in,
                              void* d_out, int out_size) {
    const float* x           = (const float*)d_in[0];
    const float* ln_g        = (const float*)d_in[1];
    const float* ln_b        = (const float*)d_in[2];
    const float* qkv_w       = (const float*)d_in[3];
    const float* temperature = (const float*)d_in[4];
    const float* proj_w      = (const float*)d_in[5];
    const float* proj_b      = (const float*)d_in[6];
    float* out = (float*)d_out;

    cudaFuncSetAttribute(mmagemm<0>, cudaFuncAttributeMaxDynamicSharedMemorySize, GEMM_SMEM);
    cudaFuncSetAttribute(mmagemm<1>, cudaFuncAttributeMaxDynamicSharedMemorySize, GEMM_SMEM);
    cudaFuncSetAttribute(attn_v_mma, cudaFuncAttributeMaxDynamicSharedMemorySize, AV_SMEM);

    round_w_kernel<<<512, 256>>>(qkv_w, proj_w);
    ln_kernel<<<Tt, 128>>>(x, ln_g, ln_b);
    mmagemm<0><<<dim3(1536/256, Tt/128), 256, GEMM_SMEM>>>(nullptr, nullptr);
    attn_qk_mma<<<dim3(64, NSPLIT), 128>>>();
    softmax_kernel<<<64, 256>>>(temperature);
    attn_v_mma<<<dim3(64, 32), 256, AV_SMEM>>>();
    mmagemm<1><<<dim3(512/256, Tt/128), 256, GEMM_SMEM>>>(proj_b, out);
}

// round 9
// speedup vs baseline: 1.9054x; 1.4292x over previous
#include <cuda_runtime.h>
#include <cuda_fp16.h>
#include <math.h>
#include <stdint.h>

#define Bb 8
#define Nn 4096
#define Cc 512
#define Hh 8
#define DHd 64
#define Tt (Bb*Nn)   // 32768 tokens
#define NSPLIT 16

// Scratch (allocation-free rule: device globals)
__device__ __half g_xn[Tt*Cc];                // LayerNorm output [T,C], fp16
__device__ __half g_qkv[3*Bb*Hh*DHd*Nn];      // [i][b][h][d][n], fp16
__device__ __half g_y[Tt*Cc];                 // gelu(attn@v) [T,C], fp16
__device__ float  g_Sp[64*NSPLIT*64*64];      // partial raw S (fp32)
__device__ float  g_ss[2*64*NSPLIT*64];       // partial sum-of-squares (fp32)
__device__ __half g_attn[64*64*64];           // softmaxed attn [bh][d][e], fp16
__device__ __half g_wq[1536*512];             // fp16 qkv_w
__device__ __half g_wp[512*512];              // fp16 proj_w

__device__ __forceinline__ uint32_t smem_u32(const void* p) {
    uint32_t a;
    asm("{ .reg .u64 t; cvta.to.shared.u64 t, %1; cvt.u32.u64 %0, t; }"
        : "=r"(a) : "l"(p));
    return a;
}
__device__ __forceinline__ void cp16(uint32_t daddr, const void* src) {
    asm volatile("{ .reg .u64 p; cvta.to.global.u64 p, %1;"
                 "  cp.async.cg.shared.global [%0], [p], 16; }"
                 :: "r"(daddr), "l"(src) : "memory");
}
#define LDM_X4(a0,a1,a2,a3,addr) \
    asm volatile("ldmatrix.sync.aligned.m8n8.x4.shared.b16 {%0,%1,%2,%3}, [%4];" \
        : "=r"(a0), "=r"(a1), "=r"(a2), "=r"(a3) : "r"(addr))
#define LDM_X2(b0,b1,addr) \
    asm volatile("ldmatrix.sync.aligned.m8n8.x2.shared.b16 {%0,%1}, [%2];" \
        : "=r"(b0), "=r"(b1) : "r"(addr))
#define MMA_F16(c0,c1,c2,c3,a0,a1,a2,a3,b0,b1) \
    asm volatile("mma.sync.aligned.m16n8k16.row.col.f32.f16.f16.f32 " \
        "{%0,%1,%2,%3}, {%4,%5,%6,%7}, {%8,%9}, {%0,%1,%2,%3};" \
        : "+f"(c0), "+f"(c1), "+f"(c2), "+f"(c3) \
        : "r"(a0), "r"(a1), "r"(a2), "r"(a3), "r"(b0), "r"(b1))

// ===========================================================================
// K0: convert weights to fp16
// ===========================================================================
__global__ void round_w_kernel(const float* __restrict__ qkv_w,
                               const float* __restrict__ proj_w) {
    const int n1 = 1536*512/4, n2 = 512*512/4;
    for (int i = blockIdx.x*blockDim.x + threadIdx.x; i < n1 + n2;
         i += gridDim.x*blockDim.x) {
        const float4 v = (i < n1) ? ((const float4*)qkv_w)[i]
                                  : ((const float4*)proj_w)[i - n1];
        __half2 p0 = __floats2half2_rn(v.x, v.y);
        __half2 p1 = __floats2half2_rn(v.z, v.w);
        __half* dst = (i < n1) ? (g_wq + (size_t)i*4) : (g_wp + (size_t)(i - n1)*4);
        *(__half2*)dst = p0;
        *(__half2*)(dst + 2) = p1;
    }
}

// ===========================================================================
// K1: LayerNorm (outputs fp16)
// ===========================================================================
__global__ void ln_kernel(const float* __restrict__ x,
                          const float* __restrict__ gam,
                          const float* __restrict__ bet) {
    const int t = blockIdx.x;
    const int tid = threadIdx.x;           // 128
    const float4 xv = *(const float4*)(x + (size_t)t*Cc + tid*4);
    float s  = xv.x + xv.y + xv.z + xv.w;
    float ss = xv.x*xv.x + xv.y*xv.y + xv.z*xv.z + xv.w*xv.w;
    #pragma unroll
    for (int o = 16; o > 0; o >>= 1) {
        s  += __shfl_xor_sync(0xffffffffu, s,  o);
        ss += __shfl_xor_sync(0xffffffffu, ss, o);
    }
    __shared__ float shs[4], shss[4];
    const int w = tid >> 5, l = tid & 31;
    if (l == 0) { shs[w] = s; shss[w] = ss; }
    __syncthreads();
    const float tot  = shs[0]  + shs[1]  + shs[2]  + shs[3];
    const float tots = shss[0] + shss[1] + shss[2] + shss[3];
    const float mean = tot * (1.0f/512.0f);
    const float var  = tots * (1.0f/512.0f) - mean*mean;
    const float inv  = rsqrtf(var + 1e-5f);
    const float4 gv = *(const float4*)(gam + tid*4);
    const float4 bv = *(const float4*)(bet + tid*4);
    __half2 p0 = __floats2half2_rn((xv.x - mean)*inv*gv.x + bv.x,
                                   (xv.y - mean)*inv*gv.y + bv.y);
    __half2 p1 = __floats2half2_rn((xv.z - mean)*inv*gv.z + bv.z,
                                   (xv.w - mean)*inv*gv.w + bv.w);
    __half* dst = g_xn + (size_t)t*Cc + tid*4;
    *(__half2*)dst = p0;
    *(__half2*)(dst + 2) = p1;
}

// ===========================================================================
// fp16 mma.sync GEMM: C[t,o] = sum_c A[t,c]*W[o,c].
// Block 128(m) x 256(n), 256 thr (8 warps, 2x4), warp tile 64x64.
// Smem rows LDKH=40 halves (80B, conflict-free ldmatrix), k-chunk 32,
// cp.async 3-stage pipeline, mma m16n8k16.
// EPI=0: A=g_xn, W=g_wq -> scatter g_qkv (fp16).  EPI=1: A=g_y, W=g_wp -> out+bias.
// ===========================================================================
#define LDKH 40
#define A_BYTES (128*LDKH*2)     // 10240
#define W_BYTES (256*LDKH*2)     // 20480
#define BUF_BYTES (A_BYTES + W_BYTES)  // 30720
#define GEMM_SMEM (3*BUF_BYTES)        // 92160

template<int EPI>
__global__ void __launch_bounds__(256, 1) mmagemm(const float* __restrict__ bias,
                                                  float* __restrict__ out) {
    extern __shared__ char smem[];
    const uint32_t sb = smem_u32(smem);
    const __half* __restrict__ A = (EPI == 0) ? g_xn : g_y;
    const __half* __restrict__ W = (EPI == 0) ? g_wq : g_wp;
    const int tid = threadIdx.x;
    const int wid = tid >> 5, lane = tid & 31;
    const int t0 = blockIdx.y * 128;
    const int o0 = blockIdx.x * 256;
    const int wm = wid >> 2, wn = wid & 3;
    const int g = lane >> 2, tg = lane & 3;

    // staging mapping (16B = 8 halves per task)
    int ra[2], ca[2], rw[4], cw[4];
    #pragma unroll
    for (int j = 0; j < 2; j++) { const int idx = j*256 + tid; ra[j] = idx >> 2; ca[j] = (idx & 3)*8; }
    #pragma unroll
    for (int j = 0; j < 4; j++) { const int idx = j*256 + tid; rw[j] = idx >> 2; cw[j] = (idx & 3)*8; }

    const uint32_t baseA = sb + (uint32_t)(((wm*64 + (lane & 15))*LDKH + ((lane & 16) ? 8 : 0)) * 2);
    const uint32_t baseB = sb + A_BYTES + (uint32_t)(((wn*64 + (lane & 7))*LDKH + ((lane & 8) ? 8 : 0)) * 2);

    float acc[4][8][4];
    #pragma unroll
    for (int mt = 0; mt < 4; mt++)
        #pragma unroll
        for (int nt = 0; nt < 8; nt++)
            #pragma unroll
            for (int r = 0; r < 4; r++) acc[mt][nt][r] = 0.0f;

    #pragma unroll
    for (int s = 0; s < 2; s++) {
        const uint32_t sA = sb + s*BUF_BYTES, sW = sA + A_BYTES;
        const int k0 = s * 32;
        #pragma unroll
        for (int j = 0; j < 2; j++)
            cp16(sA + (ra[j]*LDKH + ca[j])*2, A + (size_t)(t0 + ra[j])*512 + k0 + ca[j]);
        #pragma unroll
        for (int j = 0; j < 4; j++)
            cp16(sW + (rw[j]*LDKH + cw[j])*2, W + (size_t)(o0 + rw[j])*512 + k0 + cw[j]);
        asm volatile("cp.async.commit_group;" ::: "memory");
    }

    for (int c = 0; c < 16; c++) {
        if (c < 15) asm volatile("cp.async.wait_group 1;" ::: "memory");
        else        asm volatile("cp.async.wait_group 0;" ::: "memory");
        __syncthreads();
        if (c + 2 < 16) {
            const int k0 = (c + 2) * 32;
            const uint32_t sA = sb + ((c + 2) % 3)*BUF_BYTES;
            const uint32_t sW = sA + A_BYTES;
            #pragma unroll
            for (int j = 0; j < 2; j++)
                cp16(sA + (ra[j]*LDKH + ca[j])*2, A + (size_t)(t0 + ra[j])*512 + k0 + ca[j]);
            #pragma unroll
            for (int j = 0; j < 4; j++)
                cp16(sW + (rw[j]*LDKH + cw[j])*2, W + (size_t)(o0 + rw[j])*512 + k0 + cw[j]);
            asm volatile("cp.async.commit_group;" ::: "memory");
        }
        const uint32_t aoff = baseA + (c % 3)*BUF_BYTES;
        const uint32_t boff = baseB + (c % 3)*BUF_BYTES;
        #pragma unroll
        for (int ks = 0; ks < 2; ks++) {
            uint32_t a[4][4], b[8][2];
            #pragma unroll
            for (int mt = 0; mt < 4; mt++)
                LDM_X4(a[mt][0], a[mt][1], a[mt][2], a[mt][3],
                       aoff + (uint32_t)((mt*16*LDKH + ks*16) * 2));
            #pragma unroll
            for (int nt = 0; nt < 8; nt++)
                LDM_X2(b[nt][0], b[nt][1], boff + (uint32_t)((nt*8*LDKH + ks*16) * 2));
            #pragma unroll
            for (int mt = 0; mt < 4; mt++)
                #pragma unroll
                for (int nt = 0; nt < 8; nt++)
                    MMA_F16(acc[mt][nt][0], acc[mt][nt][1], acc[mt][nt][2], acc[mt][nt][3],
                            a[mt][0], a[mt][1], a[mt][2], a[mt][3], b[nt][0], b[nt][1]);
        }
    }

    const int m0g = t0 + wm*64;
    const int o0g = o0 + wn*64;
    if (EPI == 0) {
        const int i_ = o0g >> 9;
        const int h  = (o0g >> 6) & 7;
        const int b  = m0g >> 12;
        const int rowbase = ((i_*8 + b)*8 + h) * 64;
        #pragma unroll
        for (int mt = 0; mt < 4; mt++) {
            const int t1 = m0g + mt*16 + g;
            const int n1 = t1 & 4095;
            #pragma unroll
            for (int nt = 0; nt < 8; nt++) {
                const int row = rowbase + nt*8 + tg*2;
                g_qkv[(size_t)row*4096 + n1]            = __float2half(acc[mt][nt][0]);
                g_qkv[(size_t)(row + 1)*4096 + n1]      = __float2half(acc[mt][nt][1]);
                g_qkv[(size_t)row*4096 + n1 + 8]        = __float2half(acc[mt][nt][2]);
                g_qkv[(size_t)(row + 1)*4096 + n1 + 8]  = __float2half(acc[mt][nt][3]);
            }
        }
    } else {
        #pragma unroll
        for (int mt = 0; mt < 4; mt++) {
            const int t1 = m0g + mt*16 + g;
            #pragma unroll
            for (int nt = 0; nt < 8; nt++) {
                const int o = o0g + nt*8 + tg*2;
                const float b0 = bias[o], b1 = bias[o + 1];
                float2 v0; v0.x = acc[mt][nt][0] + b0; v0.y = acc[mt][nt][1] + b1;
                float2 v1; v1.x = acc[mt][nt][2] + b0; v1.y = acc[mt][nt][3] + b1;
                *(float2*)(out + (size_t)t1*512 + o)       = v0;
                *(float2*)(out + (size_t)(t1 + 8)*512 + o) = v1;
            }
        }
    }
}

// ===========================================================================
// K4a: fp16 mma S-partials: per (bh, split) a 64x64x256 GEMM. 128 thr.
// Also accumulates per-row sum-of-squares (of fp16-rounded q,k) partials.
// ===========================================================================
#define QLDKH 40
__global__ void __launch_bounds__(128) attn_qk_mma() {
    __shared__ __half qs[64*QLDKH];
    __shared__ __half ks_[64*QLDKH];
    const int bh = blockIdx.x;
    const int split = blockIdx.y;
    const __half* __restrict__ q = g_qkv + (size_t)bh * 64 * 4096;
    const __half* __restrict__ k = g_qkv + (size_t)(64 + bh) * 64 * 4096;
    const int tid = threadIdx.x;
    const int wid = tid >> 5, lane = tid & 31;
    const uint32_t sq = smem_u32(qs), sk = smem_u32(ks_);
    const int r0 = tid >> 2;              // 0..31
    const int c8 = (tid & 3) * 8;         // 0,8,16,24

    const uint32_t aoff = sq + (uint32_t)(((wid*16 + (lane & 15))*QLDKH + ((lane & 16) ? 8 : 0)) * 2);
    const uint32_t boff = sk + (uint32_t)(((lane & 7)*QLDKH + ((lane & 8) ? 8 : 0)) * 2);

    float acc[8][4];
    #pragma unroll
    for (int nt = 0; nt < 8; nt++)
        #pragma unroll
        for (int r = 0; r < 4; r++) acc[nt][r] = 0.0f;
    float ssq[2] = {0,0}, ssk[2] = {0,0};

    for (int ch = 0; ch < 8; ch++) {
        const int n0 = split*256 + ch*32;
        #pragma unroll
        for (int j = 0; j < 2; j++) {
            const int row = j*32 + r0;
            const float4 qv = *(const float4*)(q + (size_t)row*4096 + n0 + c8);
            *(float4*)&qs[row*QLDKH + c8] = qv;
            const __half2* qh = (const __half2*)&qv;
            #pragma unroll
            for (int p = 0; p < 4; p++) {
                const float2 f = __half22float2(qh[p]);
                ssq[j] += f.x*f.x + f.y*f.y;
            }
            const float4 kv = *(const float4*)(k + (size_t)row*4096 + n0 + c8);
            *(float4*)&ks_[row*QLDKH + c8] = kv;
            const __half2* kh = (const __half2*)&kv;
            #pragma unroll
            for (int p = 0; p < 4; p++) {
                const float2 f = __half22float2(kh[p]);
                ssk[j] += f.x*f.x + f.y*f.y;
            }
        }
        __syncthreads();
        #pragma unroll
        for (int ks = 0; ks < 2; ks++) {
            uint32_t a[4], b[8][2];
            LDM_X4(a[0], a[1], a[2], a[3], aoff + (uint32_t)((ks*16) * 2));
            #pragma unroll
            for (int nt = 0; nt < 8; nt++)
                LDM_X2(b[nt][0], b[nt][1], boff + (uint32_t)((nt*8*QLDKH + ks*16) * 2));
            #pragma unroll
            for (int nt = 0; nt < 8; nt++)
                MMA_F16(acc[nt][0], acc[nt][1], acc[nt][2], acc[nt][3],
                        a[0], a[1], a[2], a[3], b[nt][0], b[nt][1]);
        }
        __syncthreads();
    }
    // reduce ss over the 4 lanes (tid&3) sharing each row
    #pragma unroll
    for (int o = 1; o < 4; o <<= 1) {
        #pragma unroll
        for (int j = 0; j < 2; j++) {
            ssq[j] += __shfl_xor_sync(0xffffffffu, ssq[j], o);
            ssk[j] += __shfl_xor_sync(0xffffffffu, ssk[j], o);
        }
    }
    if ((tid & 3) == 0) {
        #pragma unroll
        for (int j = 0; j < 2; j++) {
            const int row = j*32 + r0;
            g_ss[((size_t)bh*NSPLIT + split)*64 + row]        = ssq[j];
            g_ss[((size_t)(64 + bh)*NSPLIT + split)*64 + row] = ssk[j];
        }
    }
    // write partial S (float2, m16n8 C layout), fp32
    float* dst = g_Sp + ((size_t)(bh*NSPLIT + split)) * 4096;
    const int g = lane >> 2, tg = lane & 3;
    const int d0 = wid*16 + g;
    #pragma unroll
    for (int nt = 0; nt < 8; nt++) {
        const int e = nt*8 + tg*2;
        float2 v0; v0.x = acc[nt][0]; v0.y = acc[nt][1];
        float2 v1; v1.x = acc[nt][2]; v1.y = acc[nt][3];
        *(float2*)(dst + d0*64 + e)       = v0;
        *(float2*)(dst + (d0 + 8)*64 + e) = v1;
    }
}

// ===========================================================================
// K4b: reduce NSPLIT partials, apply norm scales * temperature, softmax over e.
// Output fp16.
// ===========================================================================
#define PAD 65
__global__ void __launch_bounds__(256) softmax_kernel(const float* __restrict__ temperature) {
    __shared__ float S[64*PAD];
    __shared__ float scq[64], sck[64];
    const int bh = blockIdx.x;
    const int tid = threadIdx.x;
    for (int idx = tid; idx < 4096; idx += 256) {
        float s = 0.0f;
        #pragma unroll
        for (int sp = 0; sp < NSPLIT; sp++)
            s += g_Sp[((size_t)(bh*NSPLIT + sp))*4096 + idx];
        S[(idx >> 6)*PAD + (idx & 63)] = s;
    }
    if (tid < 128) {
        const int iq = tid >> 6;
        const int r = tid & 63;
        float s = 0.0f;
        #pragma unroll
        for (int sp = 0; sp < NSPLIT; sp++)
            s += g_ss[((size_t)(iq*64 + bh)*NSPLIT + sp)*64 + r];
        const float nrm = fmaxf(sqrtf(s), 1e-12f);
        if (iq == 0) scq[r] = temperature[bh & 7] / nrm;
        else         sck[r] = 1.0f / nrm;
    }
    __syncthreads();
    if (tid < 64) {
        const int d = tid;
        const float qsc = scq[d];
        float mx = -1e30f;
        #pragma unroll 8
        for (int e = 0; e < 64; e++) {
            const float v = S[d*PAD + e] * qsc * sck[e];
            S[d*PAD + e] = v;
            mx = fmaxf(mx, v);
        }
        float sm = 0.0f;
        #pragma unroll 8
        for (int e = 0; e < 64; e++) {
            const float ex = __expf(S[d*PAD + e] - mx);
            S[d*PAD + e] = ex;
            sm += ex;
        }
        const float inv = 1.0f / sm;
        #pragma unroll 8
        for (int e = 0; e < 64; e++)
            g_attn[(size_t)bh*4096 + d*64 + e] = __float2half(S[d*PAD + e] * inv);
    }
}

// ===========================================================================
// K4c: fp16 mma attn@v + GELU. Per (bh, n-chunk of 128): 64x128x64 GEMM.
// 256 thr, 8 warps (4x2): warp tile 16(m) x 64(n). B = v^T staged in smem.
// ===========================================================================
#define VLDAH 72
__global__ void __launch_bounds__(256) attn_v_mma() {
    __shared__ __half As[64*VLDAH];    // attn [d][e]
    __shared__ __half Bs[128*VLDAH];   // v^T  [n][e]
    const int bh = blockIdx.x;
    const int b = bh >> 3, h = bh & 7;
    const int n0 = blockIdx.y * 128;
    const __half* __restrict__ v = g_qkv + (size_t)(128 + bh) * 64 * 4096;
    const int tid = threadIdx.x;
    const int wid = tid >> 5, lane = tid & 31;
    const int wm = wid >> 1, wn = wid & 1;

    // stage attn (4096 halves = 512 x 16B)
    #pragma unroll
    for (int j = 0; j < 2; j++) {
        const int idx = j*256 + tid;
        const int d = idx >> 3;
        const int e8 = (idx & 7) * 8;
        *(float4*)&As[d*VLDAH + e8] =
            *(const float4*)(g_attn + (size_t)bh*4096 + d*64 + e8);
    }
    // stage v transposed: v[e][n] 8-half chunks -> Bs[n][e]
    #pragma unroll
    for (int j = 0; j < 4; j++) {
        const int idx = j*256 + tid;           // 0..1023
        const int e = idx >> 4;                // 0..63
        const int n8 = (idx & 15) * 8;         // 0..120
        const float4 vv = *(const float4*)(v + (size_t)e*4096 + n0 + n8);
        const __half* hp = (const __half*)&vv;
        #pragma unroll
        for (int p = 0; p < 8; p++)
            Bs[(n8 + p)*VLDAH + e] = hp[p];
    }
    __syncthreads();

    const uint32_t sa = smem_u32(As), sbv = smem_u32(Bs);
    const uint32_t aoff = sa + (uint32_t)(((wm*16 + (lane & 15))*VLDAH + ((lane & 16) ? 8 : 0)) * 2);
    const uint32_t boff = sbv + (uint32_t)(((wn*64 + (lane & 7))*VLDAH + ((lane & 8) ? 8 : 0)) * 2);

    float acc[8][4];
    #pragma unroll
    for (int nt = 0; nt < 8; nt++)
        #pragma unroll
        for (int r = 0; r < 4; r++) acc[nt][r] = 0.0f;

    #pragma unroll
    for (int ks = 0; ks < 4; ks++) {
        uint32_t a[4], bfr[8][2];
        LDM_X4(a[0], a[1], a[2], a[3], aoff + (uint32_t)((ks*16) * 2));
        #pragma unroll
        for (int nt = 0; nt < 8; nt++)
            LDM_X2(bfr[nt][0], bfr[nt][1], boff + (uint32_t)((nt*8*VLDAH + ks*16) * 2));
        #pragma unroll
        for (int nt = 0; nt < 8; nt++)
            MMA_F16(acc[nt][0], acc[nt][1], acc[nt][2], acc[nt][3],
                    a[0], a[1], a[2], a[3], bfr[nt][0], bfr[nt][1]);
    }

    // epilogue: gelu + scatter to g_y [b,n,c] (c = h*64 + d), fp16
    const int g = lane >> 2, tg = lane & 3;
    const int d0 = wm*16 + g;
    #pragma unroll
    for (int nt = 0; nt < 8; nt++) {
        const int n = n0 + wn*64 + nt*8 + tg*2;
        const size_t t0r = (size_t)b*4096 + n;
        #pragma unroll
        for (int r = 0; r < 4; r++) {
            const int d = d0 + (r >> 1)*8;
            const size_t t = t0r + (r & 1);
            const float xg = acc[nt][r];
            g_y[t*512 + h*64 + d] =
                __float2half(0.5f*xg*(1.0f + erff(xg*0.70710678118654752f)));
        }
    }
}

// ===========================================================================
extern "C" void kernel_launch(void* const* d_in, const int* in_sizes, int n_in,
                              void* d_out, int out_size) {
    const float* x           = (const float*)d_in[0];
    const float* ln_g        = (const float*)d_in[1];
    const float* ln_b        = (const float*)d_in[2];
    const float* qkv_w       = (const float*)d_in[3];
    const float* temperature = (const float*)d_in[4];
    const float* proj_w      = (const float*)d_in[5];
    const float* proj_b      = (const float*)d_in[6];
    float* out = (float*)d_out;

    cudaFuncSetAttribute(mmagemm<0>, cudaFuncAttributeMaxDynamicSharedMemorySize, GEMM_SMEM);
    cudaFuncSetAttribute(mmagemm<1>, cudaFuncAttributeMaxDynamicSharedMemorySize, GEMM_SMEM);

    round_w_kernel<<<512, 256>>>(qkv_w, proj_w);
    ln_kernel<<<Tt, 128>>>(x, ln_g, ln_b);
    mmagemm<0><<<dim3(1536/256, Tt/128), 256, GEMM_SMEM>>>(nullptr, nullptr);
    attn_qk_mma<<<dim3(64, NSPLIT), 128>>>();
    softmax_kernel<<<64, 256>>>(temperature);
    attn_v_mma<<<dim3(64, 32), 256>>>();
    mmagemm<1><<<dim3(512/256, Tt/128), 256, GEMM_SMEM>>>(proj_b, out);
}

// round 10
// speedup vs baseline: 2.3377x; 1.2268x over previous
#include <cuda_runtime.h>
#include <cuda_fp16.h>
#include <math.h>
#include <stdint.h>

#define Bb 8
#define Nn 4096
#define Cc 512
#define Hh 8
#define DHd 64
#define Tt (Bb*Nn)   // 32768 tokens
#define NSPLIT 16

// Scratch (allocation-free rule: device globals)
__device__ __half g_xn[Tt*Cc];                // LayerNorm output [T,C], fp16
__device__ __half g_qkv[3*Bb*Hh*DHd*Nn];      // [i][b][h][d][n], fp16
__device__ __half g_y[Tt*Cc];                 // gelu(attn@v) [T,C], fp16
__device__ float  g_Sp[64*NSPLIT*64*64];      // partial raw S (fp32)
__device__ float  g_ss[2*64*NSPLIT*64];       // partial sum-of-squares (fp32)
__device__ __half g_attn[64*64*64];           // softmaxed attn [bh][d][e], fp16
__device__ __half g_wq[1536*512];             // fp16 qkv_w
__device__ __half g_wp[512*512];              // fp16 proj_w

__device__ __forceinline__ uint32_t smem_u32(const void* p) {
    uint32_t a;
    asm("{ .reg .u64 t; cvta.to.shared.u64 t, %1; cvt.u32.u64 %0, t; }"
        : "=r"(a) : "l"(p));
    return a;
}
__device__ __forceinline__ void cp16(uint32_t daddr, const void* src) {
    asm volatile("{ .reg .u64 p; cvta.to.global.u64 p, %1;"
                 "  cp.async.cg.shared.global [%0], [p], 16; }"
                 :: "r"(daddr), "l"(src) : "memory");
}
#define LDM_X4(a0,a1,a2,a3,addr) \
    asm volatile("ldmatrix.sync.aligned.m8n8.x4.shared.b16 {%0,%1,%2,%3}, [%4];" \
        : "=r"(a0), "=r"(a1), "=r"(a2), "=r"(a3) : "r"(addr))
#define LDM_X2(b0,b1,addr) \
    asm volatile("ldmatrix.sync.aligned.m8n8.x2.shared.b16 {%0,%1}, [%2];" \
        : "=r"(b0), "=r"(b1) : "r"(addr))
#define LDM_X2_T(b0,b1,addr) \
    asm volatile("ldmatrix.sync.aligned.m8n8.x2.trans.shared.b16 {%0,%1}, [%2];" \
        : "=r"(b0), "=r"(b1) : "r"(addr))
#define MMA_F16(c0,c1,c2,c3,a0,a1,a2,a3,b0,b1) \
    asm volatile("mma.sync.aligned.m16n8k16.row.col.f32.f16.f16.f32 " \
        "{%0,%1,%2,%3}, {%4,%5,%6,%7}, {%8,%9}, {%0,%1,%2,%3};" \
        : "+f"(c0), "+f"(c1), "+f"(c2), "+f"(c3) \
        : "r"(a0), "r"(a1), "r"(a2), "r"(a3), "r"(b0), "r"(b1))

// ===========================================================================
// K0: convert weights to fp16
// ===========================================================================
__global__ void round_w_kernel(const float* __restrict__ qkv_w,
                               const float* __restrict__ proj_w) {
    const int n1 = 1536*512/4, n2 = 512*512/4;
    for (int i = blockIdx.x*blockDim.x + threadIdx.x; i < n1 + n2;
         i += gridDim.x*blockDim.x) {
        const float4 v = (i < n1) ? ((const float4*)qkv_w)[i]
                                  : ((const float4*)proj_w)[i - n1];
        __half2 p0 = __floats2half2_rn(v.x, v.y);
        __half2 p1 = __floats2half2_rn(v.z, v.w);
        __half* dst = (i < n1) ? (g_wq + (size_t)i*4) : (g_wp + (size_t)(i - n1)*4);
        *(__half2*)dst = p0;
        *(__half2*)(dst + 2) = p1;
    }
}

// ===========================================================================
// K1: LayerNorm (outputs fp16)
// ===========================================================================
__global__ void ln_kernel(const float* __restrict__ x,
                          const float* __restrict__ gam,
                          const float* __restrict__ bet) {
    const int t = blockIdx.x;
    const int tid = threadIdx.x;           // 128
    const float4 xv = *(const float4*)(x + (size_t)t*Cc + tid*4);
    float s  = xv.x + xv.y + xv.z + xv.w;
    float ss = xv.x*xv.x + xv.y*xv.y + xv.z*xv.z + xv.w*xv.w;
    #pragma unroll
    for (int o = 16; o > 0; o >>= 1) {
        s  += __shfl_xor_sync(0xffffffffu, s,  o);
        ss += __shfl_xor_sync(0xffffffffu, ss, o);
    }
    __shared__ float shs[4], shss[4];
    const int w = tid >> 5, l = tid & 31;
    if (l == 0) { shs[w] = s; shss[w] = ss; }
    __syncthreads();
    const float tot  = shs[0]  + shs[1]  + shs[2]  + shs[3];
    const float tots = shss[0] + shss[1] + shss[2] + shss[3];
    const float mean = tot * (1.0f/512.0f);
    const float var  = tots * (1.0f/512.0f) - mean*mean;
    const float inv  = rsqrtf(var + 1e-5f);
    const float4 gv = *(const float4*)(gam + tid*4);
    const float4 bv = *(const float4*)(bet + tid*4);
    __half2 p0 = __floats2half2_rn((xv.x - mean)*inv*gv.x + bv.x,
                                   (xv.y - mean)*inv*gv.y + bv.y);
    __half2 p1 = __floats2half2_rn((xv.z - mean)*inv*gv.z + bv.z,
                                   (xv.w - mean)*inv*gv.w + bv.w);
    __half* dst = g_xn + (size_t)t*Cc + tid*4;
    *(__half2*)dst = p0;
    *(__half2*)(dst + 2) = p1;
}

// ===========================================================================
// fp16 mma.sync GEMM: C[t,o] = sum_c A[t,c]*W[o,c].
// Block 128(m) x 256(n), 512 thr (16 warps, 4x4), warp tile 32x64.
// LDKH=40 halves/row, k-chunk 32, cp.async 3-stage, mma m16n8k16.
// ===========================================================================
#define LDKH 40
#define A_BYTES (128*LDKH*2)     // 10240
#define W_BYTES (256*LDKH*2)     // 20480
#define BUF_BYTES (A_BYTES + W_BYTES)  // 30720
#define GEMM_SMEM (3*BUF_BYTES)        // 92160

template<int EPI>
__global__ void __launch_bounds__(512, 1) mmagemm(const float* __restrict__ bias,
                                                  float* __restrict__ out) {
    extern __shared__ char smem[];
    const uint32_t sb = smem_u32(smem);
    const __half* __restrict__ A = (EPI == 0) ? g_xn : g_y;
    const __half* __restrict__ W = (EPI == 0) ? g_wq : g_wp;
    const int tid = threadIdx.x;
    const int wid = tid >> 5, lane = tid & 31;
    const int t0 = blockIdx.y * 128;
    const int o0 = blockIdx.x * 256;
    const int wm = wid >> 2, wn = wid & 3;   // 4 x 4 warp grid
    const int g = lane >> 2, tg = lane & 3;

    // staging mapping (16B = 8 halves per task)
    const int ra = tid >> 2, ca = (tid & 3)*8;           // A: 512 tasks
    int rw[2], cw[2];                                     // W: 1024 tasks
    #pragma unroll
    for (int j = 0; j < 2; j++) { const int idx = j*512 + tid; rw[j] = idx >> 2; cw[j] = (idx & 3)*8; }

    const uint32_t baseA = sb + (uint32_t)(((wm*32 + (lane & 15))*LDKH + ((lane & 16) ? 8 : 0)) * 2);
    const uint32_t baseB = sb + A_BYTES + (uint32_t)(((wn*64 + (lane & 7))*LDKH + ((lane & 8) ? 8 : 0)) * 2);

    float acc[2][8][4];
    #pragma unroll
    for (int mt = 0; mt < 2; mt++)
        #pragma unroll
        for (int nt = 0; nt < 8; nt++)
            #pragma unroll
            for (int r = 0; r < 4; r++) acc[mt][nt][r] = 0.0f;

    #pragma unroll
    for (int s = 0; s < 2; s++) {
        const uint32_t sA = sb + s*BUF_BYTES, sW = sA + A_BYTES;
        const int k0 = s * 32;
        cp16(sA + (ra*LDKH + ca)*2, A + (size_t)(t0 + ra)*512 + k0 + ca);
        #pragma unroll
        for (int j = 0; j < 2; j++)
            cp16(sW + (rw[j]*LDKH + cw[j])*2, W + (size_t)(o0 + rw[j])*512 + k0 + cw[j]);
        asm volatile("cp.async.commit_group;" ::: "memory");
    }

    for (int c = 0; c < 16; c++) {
        if (c < 15) asm volatile("cp.async.wait_group 1;" ::: "memory");
        else        asm volatile("cp.async.wait_group 0;" ::: "memory");
        __syncthreads();
        if (c + 2 < 16) {
            const int k0 = (c + 2) * 32;
            const uint32_t sA = sb + ((c + 2) % 3)*BUF_BYTES;
            const uint32_t sW = sA + A_BYTES;
            cp16(sA + (ra*LDKH + ca)*2, A + (size_t)(t0 + ra)*512 + k0 + ca);
            #pragma unroll
            for (int j = 0; j < 2; j++)
                cp16(sW + (rw[j]*LDKH + cw[j])*2, W + (size_t)(o0 + rw[j])*512 + k0 + cw[j]);
            asm volatile("cp.async.commit_group;" ::: "memory");
        }
        const uint32_t aoff = baseA + (c % 3)*BUF_BYTES;
        const uint32_t boff = baseB + (c % 3)*BUF_BYTES;
        #pragma unroll
        for (int ks = 0; ks < 2; ks++) {
            uint32_t a[2][4], b[8][2];
            #pragma unroll
            for (int mt = 0; mt < 2; mt++)
                LDM_X4(a[mt][0], a[mt][1], a[mt][2], a[mt][3],
                       aoff + (uint32_t)((mt*16*LDKH + ks*16) * 2));
            #pragma unroll
            for (int nt = 0; nt < 8; nt++)
                LDM_X2(b[nt][0], b[nt][1], boff + (uint32_t)((nt*8*LDKH + ks*16) * 2));
            #pragma unroll
            for (int mt = 0; mt < 2; mt++)
                #pragma unroll
                for (int nt = 0; nt < 8; nt++)
                    MMA_F16(acc[mt][nt][0], acc[mt][nt][1], acc[mt][nt][2], acc[mt][nt][3],
                            a[mt][0], a[mt][1], a[mt][2], a[mt][3], b[nt][0], b[nt][1]);
        }
    }

    const int m0g = t0 + wm*32;
    const int o0g = o0 + wn*64;
    if (EPI == 0) {
        const int i_ = o0g >> 9;
        const int h  = (o0g >> 6) & 7;
        const int b  = m0g >> 12;
        const int rowbase = ((i_*8 + b)*8 + h) * 64;
        #pragma unroll
        for (int mt = 0; mt < 2; mt++) {
            const int t1 = m0g + mt*16 + g;
            const int n1 = t1 & 4095;
            #pragma unroll
            for (int nt = 0; nt < 8; nt++) {
                const int row = rowbase + nt*8 + tg*2;
                g_qkv[(size_t)row*4096 + n1]            = __float2half(acc[mt][nt][0]);
                g_qkv[(size_t)(row + 1)*4096 + n1]      = __float2half(acc[mt][nt][1]);
                g_qkv[(size_t)row*4096 + n1 + 8]        = __float2half(acc[mt][nt][2]);
                g_qkv[(size_t)(row + 1)*4096 + n1 + 8]  = __float2half(acc[mt][nt][3]);
            }
        }
    } else {
        #pragma unroll
        for (int mt = 0; mt < 2; mt++) {
            const int t1 = m0g + mt*16 + g;
            #pragma unroll
            for (int nt = 0; nt < 8; nt++) {
                const int o = o0g + nt*8 + tg*2;
                const float b0 = bias[o], b1 = bias[o + 1];
                float2 v0; v0.x = acc[mt][nt][0] + b0; v0.y = acc[mt][nt][1] + b1;
                float2 v1; v1.x = acc[mt][nt][2] + b0; v1.y = acc[mt][nt][3] + b1;
                *(float2*)(out + (size_t)t1*512 + o)       = v0;
                *(float2*)(out + (size_t)(t1 + 8)*512 + o) = v1;
            }
        }
    }
}

// ===========================================================================
// K4a: fp16 mma S-partials: per (bh, split) a 64x64x256 GEMM. 128 thr.
// (unchanged from R9)
// ===========================================================================
#define QLDKH 40
__global__ void __launch_bounds__(128) attn_qk_mma() {
    __shared__ __half qs[64*QLDKH];
    __shared__ __half ks_[64*QLDKH];
    const int bh = blockIdx.x;
    const int split = blockIdx.y;
    const __half* __restrict__ q = g_qkv + (size_t)bh * 64 * 4096;
    const __half* __restrict__ k = g_qkv + (size_t)(64 + bh) * 64 * 4096;
    const int tid = threadIdx.x;
    const int wid = tid >> 5, lane = tid & 31;
    const uint32_t sq = smem_u32(qs), sk = smem_u32(ks_);
    const int r0 = tid >> 2;
    const int c8 = (tid & 3) * 8;

    const uint32_t aoff = sq + (uint32_t)(((wid*16 + (lane & 15))*QLDKH + ((lane & 16) ? 8 : 0)) * 2);
    const uint32_t boff = sk + (uint32_t)(((lane & 7)*QLDKH + ((lane & 8) ? 8 : 0)) * 2);

    float acc[8][4];
    #pragma unroll
    for (int nt = 0; nt < 8; nt++)
        #pragma unroll
        for (int r = 0; r < 4; r++) acc[nt][r] = 0.0f;
    float ssq[2] = {0,0}, ssk[2] = {0,0};

    for (int ch = 0; ch < 8; ch++) {
        const int n0 = split*256 + ch*32;
        #pragma unroll
        for (int j = 0; j < 2; j++) {
            const int row = j*32 + r0;
            const float4 qv = *(const float4*)(q + (size_t)row*4096 + n0 + c8);
            *(float4*)&qs[row*QLDKH + c8] = qv;
            const __half2* qh = (const __half2*)&qv;
            #pragma unroll
            for (int p = 0; p < 4; p++) {
                const float2 f = __half22float2(qh[p]);
                ssq[j] += f.x*f.x + f.y*f.y;
            }
            const float4 kv = *(const float4*)(k + (size_t)row*4096 + n0 + c8);
            *(float4*)&ks_[row*QLDKH + c8] = kv;
            const __half2* kh = (const __half2*)&kv;
            #pragma unroll
            for (int p = 0; p < 4; p++) {
                const float2 f = __half22float2(kh[p]);
                ssk[j] += f.x*f.x + f.y*f.y;
            }
        }
        __syncthreads();
        #pragma unroll
        for (int ks = 0; ks < 2; ks++) {
            uint32_t a[4], b[8][2];
            LDM_X4(a[0], a[1], a[2], a[3], aoff + (uint32_t)((ks*16) * 2));
            #pragma unroll
            for (int nt = 0; nt < 8; nt++)
                LDM_X2(b[nt][0], b[nt][1], boff + (uint32_t)((nt*8*QLDKH + ks*16) * 2));
            #pragma unroll
            for (int nt = 0; nt < 8; nt++)
                MMA_F16(acc[nt][0], acc[nt][1], acc[nt][2], acc[nt][3],
                        a[0], a[1], a[2], a[3], b[nt][0], b[nt][1]);
        }
        __syncthreads();
    }
    #pragma unroll
    for (int o = 1; o < 4; o <<= 1) {
        #pragma unroll
        for (int j = 0; j < 2; j++) {
            ssq[j] += __shfl_xor_sync(0xffffffffu, ssq[j], o);
            ssk[j] += __shfl_xor_sync(0xffffffffu, ssk[j], o);
        }
    }
    if ((tid & 3) == 0) {
        #pragma unroll
        for (int j = 0; j < 2; j++) {
            const int row = j*32 + r0;
            g_ss[((size_t)bh*NSPLIT + split)*64 + row]        = ssq[j];
            g_ss[((size_t)(64 + bh)*NSPLIT + split)*64 + row] = ssk[j];
        }
    }
    float* dst = g_Sp + ((size_t)(bh*NSPLIT + split)) * 4096;
    const int g = lane >> 2, tg = lane & 3;
    const int d0 = wid*16 + g;
    #pragma unroll
    for (int nt = 0; nt < 8; nt++) {
        const int e = nt*8 + tg*2;
        float2 v0; v0.x = acc[nt][0]; v0.y = acc[nt][1];
        float2 v1; v1.x = acc[nt][2]; v1.y = acc[nt][3];
        *(float2*)(dst + d0*64 + e)       = v0;
        *(float2*)(dst + (d0 + 8)*64 + e) = v1;
    }
}

// ===========================================================================
// K4b: reduce NSPLIT partials, apply norm scales * temperature, softmax over e.
// ===========================================================================
#define PAD 65
__global__ void __launch_bounds__(256) softmax_kernel(const float* __restrict__ temperature) {
    __shared__ float S[64*PAD];
    __shared__ float scq[64], sck[64];
    const int bh = blockIdx.x;
    const int tid = threadIdx.x;
    for (int idx = tid; idx < 4096; idx += 256) {
        float s = 0.0f;
        #pragma unroll
        for (int sp = 0; sp < NSPLIT; sp++)
            s += g_Sp[((size_t)(bh*NSPLIT + sp))*4096 + idx];
        S[(idx >> 6)*PAD + (idx & 63)] = s;
    }
    if (tid < 128) {
        const int iq = tid >> 6;
        const int r = tid & 63;
        float s = 0.0f;
        #pragma unroll
        for (int sp = 0; sp < NSPLIT; sp++)
            s += g_ss[((size_t)(iq*64 + bh)*NSPLIT + sp)*64 + r];
        const float nrm = fmaxf(sqrtf(s), 1e-12f);
        if (iq == 0) scq[r] = temperature[bh & 7] / nrm;
        else         sck[r] = 1.0f / nrm;
    }
    __syncthreads();
    if (tid < 64) {
        const int d = tid;
        const float qsc = scq[d];
        float mx = -1e30f;
        #pragma unroll 8
        for (int e = 0; e < 64; e++) {
            const float v = S[d*PAD + e] * qsc * sck[e];
            S[d*PAD + e] = v;
            mx = fmaxf(mx, v);
        }
        float sm = 0.0f;
        #pragma unroll 8
        for (int e = 0; e < 64; e++) {
            const float ex = __expf(S[d*PAD + e] - mx);
            S[d*PAD + e] = ex;
            sm += ex;
        }
        const float inv = 1.0f / sm;
        #pragma unroll 8
        for (int e = 0; e < 64; e++)
            g_attn[(size_t)bh*4096 + d*64 + e] = __float2half(S[d*PAD + e] * inv);
    }
}

// ===========================================================================
// K4c: fp16 mma attn@v + GELU. Per (bh, n-chunk of 128): 64x128x64 GEMM.
// 256 thr, 8 warps (4m x 2n), warp tile 16x64. V kept [e][n] in smem
// (cp.async), B fragments via ldmatrix.trans.
// ===========================================================================
#define ALD 72     // As row stride (halves): attn [d][e]
#define VLD 136    // Vs row stride (halves): v [e][n]
__global__ void __launch_bounds__(256) attn_v_mma() {
    __shared__ __half As[64*ALD];
    __shared__ __half Vs[64*VLD];
    const int bh = blockIdx.x;
    const int b = bh >> 3, h = bh & 7;
    const int n0 = blockIdx.y * 128;
    const __half* __restrict__ v = g_qkv + (size_t)(128 + bh) * 64 * 4096;
    const int tid = threadIdx.x;
    const int wid = tid >> 5, lane = tid & 31;
    const int wm = wid >> 1, wn = wid & 1;
    const uint32_t sa = smem_u32(As), sv = smem_u32(Vs);

    // cp.async stage attn: 512 tasks (d 0..63, e8 0..56)
    #pragma unroll
    for (int j = 0; j < 2; j++) {
        const int idx = j*256 + tid;
        const int d = idx >> 3;
        const int e8 = (idx & 7) * 8;
        cp16(sa + (d*ALD + e8)*2, g_attn + (size_t)bh*4096 + d*64 + e8);
    }
    // cp.async stage v [e][n]: 1024 tasks (e 0..63, n8 0..120)
    #pragma unroll
    for (int j = 0; j < 4; j++) {
        const int idx = j*256 + tid;
        const int e = idx >> 4;
        const int n8 = (idx & 15) * 8;
        cp16(sv + (e*VLD + n8)*2, v + (size_t)e*4096 + n0 + n8);
    }
    asm volatile("cp.async.commit_group;" ::: "memory");
    asm volatile("cp.async.wait_group 0;" ::: "memory");
    __syncthreads();

    const uint32_t aoff = sa + (uint32_t)(((wm*16 + (lane & 15))*ALD + ((lane & 16) ? 8 : 0)) * 2);
    // trans B: row = ks*16 + (lane&15) (e), col = wn*64 + nt*8 (n)
    const uint32_t boff = sv + (uint32_t)(((lane & 15)*VLD + wn*64) * 2);

    float acc[8][4];
    #pragma unroll
    for (int nt = 0; nt < 8; nt++)
        #pragma unroll
        for (int r = 0; r < 4; r++) acc[nt][r] = 0.0f;

    #pragma unroll
    for (int ks = 0; ks < 4; ks++) {
        uint32_t a[4], bfr[8][2];
        LDM_X4(a[0], a[1], a[2], a[3], aoff + (uint32_t)((ks*16) * 2));
        #pragma unroll
        for (int nt = 0; nt < 8; nt++)
            LDM_X2_T(bfr[nt][0], bfr[nt][1],
                     boff + (uint32_t)((ks*16*VLD + nt*8) * 2));
        #pragma unroll
        for (int nt = 0; nt < 8; nt++)
            MMA_F16(acc[nt][0], acc[nt][1], acc[nt][2], acc[nt][3],
                    a[0], a[1], a[2], a[3], bfr[nt][0], bfr[nt][1]);
    }

    // epilogue: gelu + scatter to g_y [b,n,c] (c = h*64 + d), fp16
    const int g = lane >> 2, tg = lane & 3;
    const int d0 = wm*16 + g;
    #pragma unroll
    for (int nt = 0; nt < 8; nt++) {
        const int n = n0 + wn*64 + nt*8 + tg*2;
        const size_t t0r = (size_t)b*4096 + n;
        #pragma unroll
        for (int r = 0; r < 4; r++) {
            const int d = d0 + (r >> 1)*8;
            const size_t t = t0r + (r & 1);
            const float xg = acc[nt][r];
            g_y[t*512 + h*64 + d] =
                __float2half(0.5f*xg*(1.0f + erff(xg*0.70710678118654752f)));
        }
    }
}

// ===========================================================================
extern "C" void kernel_launch(void* const* d_in, const int* in_sizes, int n_in,
                              void* d_out, int out_size) {
    const float* x           = (const float*)d_in[0];
    const float* ln_g        = (const float*)d_in[1];
    const float* ln_b        = (const float*)d_in[2];
    const float* qkv_w       = (const float*)d_in[3];
    const float* temperature = (const float*)d_in[4];
    const float* proj_w      = (const float*)d_in[5];
    const float* proj_b      = (const float*)d_in[6];
    float* out = (float*)d_out;

    cudaFuncSetAttribute(mmagemm<0>, cudaFuncAttributeMaxDynamicSharedMemorySize, GEMM_SMEM);
    cudaFuncSetAttribute(mmagemm<1>, cudaFuncAttributeMaxDynamicSharedMemorySize, GEMM_SMEM);

    round_w_kernel<<<512, 256>>>(qkv_w, proj_w);
    ln_kernel<<<Tt, 128>>>(x, ln_g, ln_b);
    mmagemm<0><<<dim3(1536/256, Tt/128), 512, GEMM_SMEM>>>(nullptr, nullptr);
    attn_qk_mma<<<dim3(64, NSPLIT), 128>>>();
    softmax_kernel<<<64, 256>>>(temperature);
    attn_v_mma<<<dim3(64, 32), 256>>>();
    mmagemm<1><<<dim3(512/256, Tt/128), 512, GEMM_SMEM>>>(proj_b, out);
}